// round 1
// baseline (speedup 1.0000x reference)
#include <cuda_runtime.h>
#include <math.h>

// Problem constants (fixed by reference): B=2, C=128, H=W=128, RATE=2 -> 64x64 grid
#define HD 64
#define PN 4096            // 64*64 patches / pixels (downsampled)
#define CC 128
#define HI 128
#define MW 2048            // C * 16 taps (4x4 raw patch)

// Scratch (static device globals; allocation is forbidden)
__device__ float g_S[PN * PN];     // S0, then F1 (fuse pass 1)
__device__ float g_T[PN * PN];     // T (normalized 9-tap), then Z, then att
__device__ float g_W[PN * MW];     // W matrix [p][c*16+ky*4+kx]
__device__ float g_G[MW * PN];     // deconv GEMM result [ckk][q]
__device__ float g_Fd[CC * PN];    // f_ds, c-major [c][q]
__device__ float g_Bd[CC * PN];    // b_ds, c-major [c][p]
__device__ float g_n2[PN];
__device__ float g_norm[PN];
__device__ float g_mm[PN];

// ---------------------------------------------------------------- pack ds
__global__ void k_pack(const float* __restrict__ f, const float* __restrict__ b, int item) {
    int idx = blockIdx.x * blockDim.x + threadIdx.x;
    if (idx >= CC * PN) return;
    int c = idx >> 12;
    int q = idx & 4095;
    int y = q >> 6, x = q & 63;
    size_t base = ((size_t)item * CC + c) * HI * HI + (size_t)(2 * y) * HI + 2 * x;
    g_Fd[idx] = f[base];
    g_Bd[idx] = b[base];
}

// ------------------------------------------------- per-patch stats (n2, mm)
__global__ void k_stats(const float* __restrict__ mask, int item) {
    int p = blockIdx.x * blockDim.x + threadIdx.x;
    if (p >= PN) return;
    float s = 0.f;
    for (int c = 0; c < CC; c++) {
        float v = g_Bd[c * PN + p];
        s += v * v;
    }
    g_n2[p] = s;
    // mm[p] = (mean of 3x3 patch of downsampled mask == 0) ? 1 : 0
    int ph = p >> 6, pw = p & 63;
    const float* m = mask + (size_t)item * HI * HI;
    float ms = 0.f;
    for (int dh = -1; dh <= 1; dh++)
        for (int dw = -1; dw <= 1; dw++) {
            int yy = ph + dh, xx = pw + dw;
            if ((unsigned)yy < 64u && (unsigned)xx < 64u)
                ms += m[(2 * yy) * HI + 2 * xx];
        }
    g_mm[p] = (ms / 9.0f == 0.0f) ? 1.0f : 0.0f;
}

// -------------------------------------------------------- patch norm (3x3)
__global__ void k_norm() {
    int p = blockIdx.x * blockDim.x + threadIdx.x;
    if (p >= PN) return;
    int ph = p >> 6, pw = p & 63;
    float s = 0.f;
    for (int dh = -1; dh <= 1; dh++)
        for (int dw = -1; dw <= 1; dw++) {
            int yy = ph + dh, xx = pw + dw;
            if ((unsigned)yy < 64u && (unsigned)xx < 64u)
                s += g_n2[yy * 64 + xx];
        }
    // sum(wi*wi + 1e-4) over 128*3*3 elements = sum wi^2 + 0.1152
    g_norm[p] = sqrtf(s + 0.1152f);
}

// --------------------------------------------------------------- SGEMM
// C[M][N] = sum_k A[k][M] * B[k][N]   (both operands K-major rows)
__global__ __launch_bounds__(256) void sgemm_kn(const float* __restrict__ A,
                                                const float* __restrict__ B,
                                                float* __restrict__ Cm,
                                                int M, int N, int K) {
    __shared__ float As[8][128];
    __shared__ float Bs[8][128];
    int bm = blockIdx.y * 128, bn = blockIdx.x * 128;
    int tid = threadIdx.x;
    int lr = tid >> 5;              // 0..7
    int lc = (tid & 31) * 4;        // 0..124
    int ty = tid >> 4;              // 0..15
    int tx = tid & 15;              // 0..15
    float acc[8][8];
#pragma unroll
    for (int i = 0; i < 8; i++)
#pragma unroll
        for (int j = 0; j < 8; j++) acc[i][j] = 0.f;

    for (int k0 = 0; k0 < K; k0 += 8) {
        *(float4*)&As[lr][lc] = *(const float4*)&A[(size_t)(k0 + lr) * M + bm + lc];
        *(float4*)&Bs[lr][lc] = *(const float4*)&B[(size_t)(k0 + lr) * N + bn + lc];
        __syncthreads();
#pragma unroll
        for (int k = 0; k < 8; k++) {
            float ar[8], br[8];
#pragma unroll
            for (int i = 0; i < 8; i++) ar[i] = As[k][ty * 8 + i];
#pragma unroll
            for (int j = 0; j < 8; j++) br[j] = Bs[k][tx * 8 + j];
#pragma unroll
            for (int i = 0; i < 8; i++)
#pragma unroll
                for (int j = 0; j < 8; j++) acc[i][j] += ar[i] * br[j];
        }
        __syncthreads();
    }
#pragma unroll
    for (int i = 0; i < 8; i++) {
        float4 v0 = make_float4(acc[i][0], acc[i][1], acc[i][2], acc[i][3]);
        float4 v1 = make_float4(acc[i][4], acc[i][5], acc[i][6], acc[i][7]);
        size_t row = (size_t)(bm + ty * 8 + i) * N + bn + tx * 8;
        *(float4*)&Cm[row] = v0;
        *(float4*)&Cm[row + 4] = v1;
    }
}

// ------------------------------ 9-tap diagonal gather + per-patch normalize
// T[p][q] = (sum over valid (dh,dw) of S0[p+d, q+d]) / norm[p]
__global__ __launch_bounds__(256) void k_tap9() {
    int idx = blockIdx.x * 256 + threadIdx.x;
    int p = idx >> 12, q = idx & 4095;
    int ph = p >> 6, pw = p & 63, qh = q >> 6, qw = q & 63;
    float s = 0.f;
#pragma unroll
    for (int dh = -1; dh <= 1; dh++) {
        if ((unsigned)(ph + dh) >= 64u || (unsigned)(qh + dh) >= 64u) continue;
#pragma unroll
        for (int dw = -1; dw <= 1; dw++) {
            if ((unsigned)(pw + dw) >= 64u || (unsigned)(qw + dw) >= 64u) continue;
            s += g_S[idx + dh * (64 * PN + 64) + dw * (PN + 1)];
        }
    }
    g_T[idx] = s / g_norm[p];
}

// ------------------------------------------------ fuse pass 1 (flat diagonal)
// F1[r][c] = T[r-1][c-1] + T[r][c] + T[r+1][c+1]  (flat indices, zero pad)
__global__ __launch_bounds__(256) void k_fuse1() {
    int idx = blockIdx.x * 256 + threadIdx.x;
    int r = idx >> 12, c = idx & 4095;
    float s = g_T[idx];
    if (r > 0 && c > 0) s += g_T[idx - PN - 1];
    if (r < PN - 1 && c < PN - 1) s += g_T[idx + PN + 1];
    g_S[idx] = s;
}

// -------------------------- fuse pass 2 (diagonal in transposed flat order)
// Z[p][q] = sum_j F1[P(r'(p)+j)][P(c'(q)+j)], r'(p)=(p%64)*64+p/64; *mm[p]
__global__ __launch_bounds__(256) void k_fuse2() {
    int idx = blockIdx.x * 256 + threadIdx.x;
    int p = idx >> 12, q = idx & 4095;
    int rp = (p & 63) * 64 + (p >> 6);
    int rq = (q & 63) * 64 + (q >> 6);
    float s = 0.f;
#pragma unroll
    for (int j = -1; j <= 1; j++) {
        int tp = rp + j, tq = rq + j;
        if ((unsigned)tp < (unsigned)PN && (unsigned)tq < (unsigned)PN) {
            int pp = (tp & 63) * 64 + (tp >> 6);
            int qq = (tq & 63) * 64 + (tq >> 6);
            s += g_S[pp * PN + qq];
        }
    }
    g_T[idx] = s * g_mm[p];
}

// ----------------------------------------- softmax over p (rows) per column q
__global__ __launch_bounds__(256) void k_softmax() {
    int q = blockIdx.x * 32 + (threadIdx.x & 31);
    int r = threadIdx.x >> 5;  // 0..7
    __shared__ float red[8][32];
    __shared__ float bval[32];

    float m = -1e30f;
    for (int p = r; p < PN; p += 8) m = fmaxf(m, 10.0f * g_T[p * PN + q]);
    red[r][threadIdx.x & 31] = m;
    __syncthreads();
    if (r == 0) {
        float t = red[0][threadIdx.x & 31];
        for (int i = 1; i < 8; i++) t = fmaxf(t, red[i][threadIdx.x & 31]);
        bval[threadIdx.x & 31] = t;
    }
    __syncthreads();
    m = bval[threadIdx.x & 31];
    __syncthreads();

    float s = 0.f;
    for (int p = r; p < PN; p += 8) s += expf(10.0f * g_T[p * PN + q] - m);
    red[r][threadIdx.x & 31] = s;
    __syncthreads();
    if (r == 0) {
        float t = 0.f;
        for (int i = 1; i < 8; i++) t += red[i][threadIdx.x & 31];
        bval[threadIdx.x & 31] = t + red[0][threadIdx.x & 31];
    }
    __syncthreads();
    float inv = 1.0f / bval[threadIdx.x & 31];

    for (int p = r; p < PN; p += 8) {
        float e = expf(10.0f * g_T[p * PN + q] - m);
        g_T[p * PN + q] = e * inv * g_mm[p];
    }
}

// --------------------------------------------- build W[p][c*16+ky*4+kx]
// raw patch of full-res b (pad 1, stride 2, k=4): b[c, 2ph-1+ky, 2pw-1+kx]
__global__ void k_buildW(const float* __restrict__ b, int item) {
    int idx = blockIdx.x * 256 + threadIdx.x;
    if (idx >= PN * MW) return;
    int p = idx >> 11;       // /2048
    int m = idx & 2047;
    int c = m >> 4;
    int kk = m & 15;
    int ky = kk >> 2, kx = kk & 3;
    int Y = 2 * (p >> 6) - 1 + ky;
    int X = 2 * (p & 63) - 1 + kx;
    float v = 0.f;
    if ((unsigned)Y < (unsigned)HI && (unsigned)X < (unsigned)HI)
        v = b[(((size_t)item * CC + c) * HI + Y) * HI + X];
    g_W[idx] = v;
}

// --------------------------------------------- scatter-gather into output
// out[c,Y,X] = 0.25 * sum over valid (ky,kx) taps of G[(c,ky,kx)][y,x]
__global__ void k_out(float* __restrict__ out, int item) {
    int idx = blockIdx.x * 256 + threadIdx.x;
    if (idx >= CC * HI * HI) return;
    int c = idx >> 14;                 // /(128*128)
    int rest = idx & 16383;
    int Y = rest >> 7, X = rest & 127;
    int pky = (Y + 1) & 1;
    int pkx = (X + 1) & 1;
    float s = 0.f;
#pragma unroll
    for (int a = 0; a < 2; a++) {
        int ky = pky + 2 * a;
        int yn = Y + 1 - ky;
        if (yn < 0) continue;
        int yy = yn >> 1;
        if (yy >= HD) continue;
#pragma unroll
        for (int bb = 0; bb < 2; bb++) {
            int kx = pkx + 2 * bb;
            int xn = X + 1 - kx;
            if (xn < 0) continue;
            int xx = xn >> 1;
            if (xx >= HD) continue;
            s += g_G[((c * 16 + ky * 4 + kx) * (size_t)PN) + yy * 64 + xx];
        }
    }
    out[(size_t)item * CC * HI * HI + idx] = 0.25f * s;
}

// ---------------------------------------------------------------- launcher
extern "C" void kernel_launch(void* const* d_in, const int* in_sizes, int n_in,
                              void* d_out, int out_size) {
    const float* f = (const float*)d_in[0];
    const float* b = (const float*)d_in[1];
    const float* mask = (const float*)d_in[2];
    float* out = (float*)d_out;

    float *pS, *pT, *pW, *pG, *pFd, *pBd;
    cudaGetSymbolAddress((void**)&pS, g_S);
    cudaGetSymbolAddress((void**)&pT, g_T);
    cudaGetSymbolAddress((void**)&pW, g_W);
    cudaGetSymbolAddress((void**)&pG, g_G);
    cudaGetSymbolAddress((void**)&pFd, g_Fd);
    cudaGetSymbolAddress((void**)&pBd, g_Bd);

    const int bigGrid = (PN * PN) / 256;  // 65536

    for (int item = 0; item < 2; item++) {
        k_pack<<<(CC * PN + 255) / 256, 256>>>(f, b, item);
        k_stats<<<(PN + 255) / 256, 256>>>(mask, item);
        k_norm<<<(PN + 255) / 256, 256>>>();

        // S0[p][q] = sum_c Bd[c][p] * Fd[c][q]   (M=N=4096, K=128)
        sgemm_kn<<<dim3(PN / 128, PN / 128), 256>>>(pBd, pFd, pS, PN, PN, CC);

        k_tap9<<<bigGrid, 256>>>();
        k_fuse1<<<bigGrid, 256>>>();
        k_fuse2<<<bigGrid, 256>>>();
        k_softmax<<<PN / 32, 256>>>();

        k_buildW<<<(PN * MW) / 256, 256>>>(b, item);
        // G[ckk][q] = sum_p W[p][ckk] * att[p][q]  (M=2048, N=4096, K=4096)
        sgemm_kn<<<dim3(PN / 128, MW / 128), 256>>>(pW, pT, pG, MW, PN, PN);

        k_out<<<(CC * HI * HI + 255) / 256, 256>>>(out, item);
    }
}

// round 3
// speedup vs baseline: 3.6154x; 3.6154x over previous
#include <cuda_runtime.h>
#include <cuda_bf16.h>
#include <math.h>
#include <stdint.h>

#define HD 64
#define PN 4096            // 64*64 downsampled pixels/patches
#define CC 128
#define HI 128
#define KP 4352            // padded 65*65=4225 -> 4352 (34*128)

// ------------------------------------------------------ device scratch
__device__ __align__(128) float g_S[PN * PN];          // S0, then F1
__device__ __align__(128) float g_T[PN * PN];          // T / Z / att
__device__ __align__(128) float g_Bd[CC * PN];
__device__ __align__(128) float g_R[512 * KP];         // deconv GEMM out
__device__ float g_n2[PN];
__device__ float g_norm[PN];
__device__ float g_mm[PN];
__device__ __align__(128) __nv_bfloat16 g_S0Ah[PN * CC];   // Bd^T [p][c] hi
__device__ __align__(128) __nv_bfloat16 g_S0Al[PN * CC];
__device__ __align__(128) __nv_bfloat16 g_S0Bh[CC * PN];   // Fd [c][q] hi
__device__ __align__(128) __nv_bfloat16 g_S0Bl[CC * PN];
__device__ __align__(128) __nv_bfloat16 g_Ah[512 * KP];    // b taps [m][kp]
__device__ __align__(128) __nv_bfloat16 g_Al[512 * KP];
__device__ __align__(128) __nv_bfloat16 g_M4h[(size_t)KP * KP];
__device__ __align__(128) __nv_bfloat16 g_M4l[(size_t)KP * KP];

// ------------------------------------------------------ PTX helpers
static __device__ __forceinline__ uint32_t smem_u32(const void* p) {
    uint32_t r;
    asm("{ .reg .u64 t; cvta.to.shared.u64 t, %1; cvt.u32.u64 %0, t; }" : "=r"(r) : "l"(p));
    return r;
}
#define CPA(s, g) asm volatile("cp.async.cg.shared.global [%0], [%1], 16;" :: "r"(s), "l"(g))
#define CPC() asm volatile("cp.async.commit_group;" ::: "memory")
#define CPW1() asm volatile("cp.async.wait_group 1;" ::: "memory")
#define LDSM4(R, a) \
    asm volatile("ldmatrix.sync.aligned.m8n8.x4.shared.b16 {%0,%1,%2,%3}, [%4];" \
        : "=r"((R)[0]), "=r"((R)[1]), "=r"((R)[2]), "=r"((R)[3]) : "r"(a))
#define LDSM4T(R, a) \
    asm volatile("ldmatrix.sync.aligned.m8n8.x4.trans.shared.b16 {%0,%1,%2,%3}, [%4];" \
        : "=r"((R)[0]), "=r"((R)[1]), "=r"((R)[2]), "=r"((R)[3]) : "r"(a))
#define MMA16816(D, A, B) \
    asm volatile("mma.sync.aligned.m16n8k16.row.col.f32.bf16.bf16.f32 " \
        "{%0,%1,%2,%3},{%4,%5,%6,%7},{%8,%9},{%0,%1,%2,%3};" \
        : "+f"((D)[0]), "+f"((D)[1]), "+f"((D)[2]), "+f"((D)[3]) \
        : "r"((A)[0]), "r"((A)[1]), "r"((A)[2]), "r"((A)[3]), "r"((B)[0]), "r"((B)[1]))

// ------------------------------------------------------ pack downsample
__global__ void k_pack(const float* __restrict__ f, const float* __restrict__ b, int item) {
    int idx = blockIdx.x * blockDim.x + threadIdx.x;
    if (idx >= CC * PN) return;
    int c = idx >> 12;
    int q = idx & 4095;
    int y = q >> 6, x = q & 63;
    size_t base = ((size_t)item * CC + c) * HI * HI + (size_t)(2 * y) * HI + 2 * x;
    float vf = f[base];
    float vb = b[base];
    g_Bd[idx] = vb;
    __nv_bfloat16 h = __float2bfloat16(vf);
    g_S0Bh[idx] = h;
    g_S0Bl[idx] = __float2bfloat16(vf - __bfloat162float(h));
    h = __float2bfloat16(vb);
    g_S0Ah[q * CC + c] = h;
    g_S0Al[q * CC + c] = __float2bfloat16(vb - __bfloat162float(h));
}

__global__ void k_stats(const float* __restrict__ mask, int item) {
    int p = blockIdx.x * blockDim.x + threadIdx.x;
    if (p >= PN) return;
    float s = 0.f;
    for (int c = 0; c < CC; c++) {
        float v = g_Bd[c * PN + p];
        s += v * v;
    }
    g_n2[p] = s;
    int ph = p >> 6, pw = p & 63;
    const float* m = mask + (size_t)item * HI * HI;
    float ms = 0.f;
    for (int dh = -1; dh <= 1; dh++)
        for (int dw = -1; dw <= 1; dw++) {
            int yy = ph + dh, xx = pw + dw;
            if ((unsigned)yy < 64u && (unsigned)xx < 64u)
                ms += m[(2 * yy) * HI + 2 * xx];
        }
    g_mm[p] = (ms / 9.0f == 0.0f) ? 1.0f : 0.0f;
}

__global__ void k_norm() {
    int p = blockIdx.x * blockDim.x + threadIdx.x;
    if (p >= PN) return;
    int ph = p >> 6, pw = p & 63;
    float s = 0.f;
    for (int dh = -1; dh <= 1; dh++)
        for (int dw = -1; dw <= 1; dw++) {
            int yy = ph + dh, xx = pw + dw;
            if ((unsigned)yy < 64u && (unsigned)xx < 64u)
                s += g_n2[yy * 64 + xx];
        }
    g_norm[p] = sqrtf(s + 0.1152f);
}

// =================================================== split-bf16 MMA GEMM
// C[M][N] = sum_k (Ah+Al)[m][k] * (Bh+Bl)[k][n]   (3-product split)
// CTA 128x128, 8 warps 32x64, K-chunk 32, cp.async double buffer.
#define SA_SZ 10240   // 128 rows * 40 bf16 * 2B
#define SB_SZ 8704    // 32 rows * 136 bf16 * 2B
#define OFF_AL (2 * SA_SZ)
#define OFF_BH (4 * SA_SZ)
#define OFF_BL (4 * SA_SZ + 2 * SB_SZ)
#define GSMEM (4 * SA_SZ + 4 * SB_SZ)   // 75776

__global__ void __launch_bounds__(256) mma_gemm(
    const __nv_bfloat16* __restrict__ Ah, const __nv_bfloat16* __restrict__ Al,
    const __nv_bfloat16* __restrict__ Bh, const __nv_bfloat16* __restrict__ Bl,
    float* __restrict__ C, int M, int N, int K) {
    extern __shared__ char smem[];
    uint32_t sb = smem_u32(smem);
    int tid = threadIdx.x;
    int lane = tid & 31, wid = tid >> 5;
    int warpM = wid >> 1, warpN = wid & 1;
    int m0 = blockIdx.y * 128, n0 = blockIdx.x * 128;

    float acc[2][8][4];
#pragma unroll
    for (int i = 0; i < 2; i++)
#pragma unroll
        for (int j = 0; j < 8; j++)
#pragma unroll
            for (int v = 0; v < 4; v++) acc[i][j][v] = 0.f;

    auto load_stage = [&](int st, int kc) {
#pragma unroll
        for (int ma = 0; ma < 2; ma++) {
            const __nv_bfloat16* src = ma ? Al : Ah;
            uint32_t sbase = sb + ma * OFF_AL + st * SA_SZ;
#pragma unroll
            for (int it = 0; it < 2; it++) {
                int idx = it * 256 + tid;
                int row = idx >> 2, seg = idx & 3;
                const void* g = src + (size_t)(m0 + row) * K + kc + seg * 8;
                CPA(sbase + (row * 40 + seg * 8) * 2, g);
            }
        }
#pragma unroll
        for (int mb = 0; mb < 2; mb++) {
            const __nv_bfloat16* src = mb ? Bl : Bh;
            uint32_t sbase = sb + OFF_BH + mb * (OFF_BL - OFF_BH) + st * SB_SZ;
#pragma unroll
            for (int it = 0; it < 2; it++) {
                int idx = it * 256 + tid;
                int row = idx >> 4, seg = idx & 15;
                const void* g = src + (size_t)(kc + row) * N + n0 + seg * 8;
                CPA(sbase + (row * 136 + seg * 8) * 2, g);
            }
        }
        CPC();
    };

    load_stage(0, 0);
    int NC = K >> 5;
    for (int c = 0; c < NC; c++) {
        if (c + 1 < NC) load_stage((c + 1) & 1, (c + 1) << 5);
        else CPC();
        CPW1();
        __syncthreads();
        int st = c & 1;
#pragma unroll
        for (int kk = 0; kk < 2; kk++) {
            uint32_t ah[2][4], al[2][4], bh[4][4], bl[4][4];
#pragma unroll
            for (int mb = 0; mb < 2; mb++) {
                uint32_t a = sb + st * SA_SZ +
                    ((warpM * 32 + mb * 16 + (lane & 15)) * 40 + kk * 16 + (lane >> 4) * 8) * 2;
                LDSM4(ah[mb], a);
                LDSM4(al[mb], a + OFF_AL);
            }
#pragma unroll
            for (int nb = 0; nb < 4; nb++) {
                uint32_t a = sb + OFF_BH + st * SB_SZ +
                    ((kk * 16 + (lane & 15)) * 136 + warpN * 64 + nb * 16 + (lane >> 4) * 8) * 2;
                LDSM4T(bh[nb], a);
                LDSM4T(bl[nb], a + (OFF_BL - OFF_BH));
            }
#pragma unroll
            for (int mb = 0; mb < 2; mb++)
#pragma unroll
                for (int nb = 0; nb < 4; nb++)
#pragma unroll
                    for (int h = 0; h < 2; h++) {
                        float* D = acc[mb][nb * 2 + h];
                        MMA16816(D, ah[mb], &bh[nb][h * 2]);
                        MMA16816(D, ah[mb], &bl[nb][h * 2]);
                        MMA16816(D, al[mb], &bh[nb][h * 2]);
                    }
        }
        __syncthreads();
    }
    int g = lane >> 2, tg = lane & 3;
#pragma unroll
    for (int mb = 0; mb < 2; mb++)
#pragma unroll
        for (int j = 0; j < 8; j++) {
            int row = m0 + warpM * 32 + mb * 16 + g;
            int col = n0 + warpN * 64 + j * 8 + tg * 2;
            float2 v0 = make_float2(acc[mb][j][0], acc[mb][j][1]);
            float2 v1 = make_float2(acc[mb][j][2], acc[mb][j][3]);
            *(float2*)&C[(size_t)row * N + col] = v0;
            *(float2*)&C[(size_t)(row + 8) * N + col] = v1;
        }
}

// ------------------------------ 9-tap diagonal gather + normalize
__global__ __launch_bounds__(256) void k_tap9() {
    int idx = blockIdx.x * 256 + threadIdx.x;
    int p = idx >> 12, q = idx & 4095;
    int ph = p >> 6, pw = p & 63, qh = q >> 6, qw = q & 63;
    float s = 0.f;
#pragma unroll
    for (int dh = -1; dh <= 1; dh++) {
        if ((unsigned)(ph + dh) >= 64u || (unsigned)(qh + dh) >= 64u) continue;
#pragma unroll
        for (int dw = -1; dw <= 1; dw++) {
            if ((unsigned)(pw + dw) >= 64u || (unsigned)(qw + dw) >= 64u) continue;
            s += g_S[idx + dh * (64 * PN + 64) + dw * (PN + 1)];
        }
    }
    g_T[idx] = s / g_norm[p];
}

__global__ __launch_bounds__(256) void k_fuse1() {
    int idx = blockIdx.x * 256 + threadIdx.x;
    int r = idx >> 12, c = idx & 4095;
    float s = g_T[idx];
    if (r > 0 && c > 0) s += g_T[idx - PN - 1];
    if (r < PN - 1 && c < PN - 1) s += g_T[idx + PN + 1];
    g_S[idx] = s;
}

__global__ __launch_bounds__(256) void k_fuse2() {
    int idx = blockIdx.x * 256 + threadIdx.x;
    int p = idx >> 12, q = idx & 4095;
    int rp = (p & 63) * 64 + (p >> 6);
    int rq = (q & 63) * 64 + (q >> 6);
    float s = 0.f;
#pragma unroll
    for (int j = -1; j <= 1; j++) {
        int tp = rp + j, tq = rq + j;
        if ((unsigned)tp < (unsigned)PN && (unsigned)tq < (unsigned)PN) {
            int pp = (tp & 63) * 64 + (tp >> 6);
            int qq = (tq & 63) * 64 + (tq >> 6);
            s += g_S[pp * PN + qq];
        }
    }
    g_T[idx] = s * g_mm[p];
}

__global__ __launch_bounds__(256) void k_softmax() {
    int q = blockIdx.x * 32 + (threadIdx.x & 31);
    int r = threadIdx.x >> 5;
    __shared__ float red[8][32];
    __shared__ float bval[32];

    float m = -1e30f;
    for (int p = r; p < PN; p += 8) m = fmaxf(m, 10.0f * g_T[p * PN + q]);
    red[r][threadIdx.x & 31] = m;
    __syncthreads();
    if (r == 0) {
        float t = red[0][threadIdx.x & 31];
        for (int i = 1; i < 8; i++) t = fmaxf(t, red[i][threadIdx.x & 31]);
        bval[threadIdx.x & 31] = t;
    }
    __syncthreads();
    m = bval[threadIdx.x & 31];
    __syncthreads();

    float s = 0.f;
    for (int p = r; p < PN; p += 8) s += expf(10.0f * g_T[p * PN + q] - m);
    red[r][threadIdx.x & 31] = s;
    __syncthreads();
    if (r == 0) {
        float t = 0.f;
        for (int i = 1; i < 8; i++) t += red[i][threadIdx.x & 31];
        bval[threadIdx.x & 31] = t + red[0][threadIdx.x & 31];
    }
    __syncthreads();
    float inv = 1.0f / bval[threadIdx.x & 31];

    for (int p = r; p < PN; p += 8) {
        float e = expf(10.0f * g_T[p * PN + q] - m);
        g_T[p * PN + q] = e * inv * g_mm[p];
    }
}

// ------------------- M4 blur: M4[p'][j] = sum_{a,b} att[(ph'-a,pw'-b)][(Y0-a,X0-b)]
__global__ void k_m4() {
    int p = blockIdx.y;
    int j = blockIdx.x * 256 + threadIdx.x;
    size_t o = (size_t)p * KP + j;
    float val = 0.f;
    if (p < 4225 && j < 4225) {
        int ph = p / 65, pw = p % 65;
        int Y0 = j / 65, X0 = j % 65;
#pragma unroll
        for (int a = 0; a < 2; a++) {
            int pa = ph - a, ya = Y0 - a;
            if ((unsigned)pa >= 64u || (unsigned)ya >= 64u) continue;
#pragma unroll
            for (int bb = 0; bb < 2; bb++) {
                int pb = pw - bb, xb = X0 - bb;
                if ((unsigned)pb >= 64u || (unsigned)xb >= 64u) continue;
                val += g_T[(size_t)(pa * 64 + pb) * PN + ya * 64 + xb];
            }
        }
    }
    __nv_bfloat16 h = __float2bfloat16(val);
    g_M4h[o] = h;
    g_M4l[o] = __float2bfloat16(val - __bfloat162float(h));
}

// ------------------- A for deconv GEMM: A[m=(cls,c)][kp=(ph',pw')] = b tap
__global__ void k_buildA(const float* __restrict__ b, int item) {
    int m = blockIdx.y;
    int kp = blockIdx.x * 256 + threadIdx.x;
    size_t o = (size_t)m * KP + kp;
    float v = 0.f;
    if (kp < 4225) {
        int cls = m >> 7, c = m & 127;
        int pky = cls >> 1, pkx = cls & 1;
        int ph = kp / 65, pw = kp % 65;
        int Y = 2 * ph - 1 + pky;
        int X = 2 * pw - 1 + pkx;
        if ((unsigned)Y < 128u && (unsigned)X < 128u)
            v = b[(((size_t)item * CC + c) * HI + Y) * HI + X];
    }
    __nv_bfloat16 h = __float2bfloat16(v);
    g_Ah[o] = h;
    g_Al[o] = __float2bfloat16(v - __bfloat162float(h));
}

// ------------------- trivial gather: one R element per output pixel
__global__ void k_out(float* __restrict__ out, int item) {
    int idx = blockIdx.x * 256 + threadIdx.x;
    if (idx >= CC * HI * HI) return;
    int c = idx >> 14;
    int Y = (idx >> 7) & 127, X = idx & 127;
    int pky = (Y + 1) & 1, pkx = (X + 1) & 1;
    int Y0 = (Y + 1) >> 1, X0 = (X + 1) >> 1;
    int cls = pky * 2 + pkx;
    out[(size_t)item * CC * HI * HI + idx] =
        0.25f * g_R[(size_t)(cls * 128 + c) * KP + Y0 * 65 + X0];
}

// ---------------------------------------------------------------- launcher
extern "C" void kernel_launch(void* const* d_in, const int* in_sizes, int n_in,
                              void* d_out, int out_size) {
    const float* f = (const float*)d_in[0];
    const float* b = (const float*)d_in[1];
    const float* mask = (const float*)d_in[2];
    float* out = (float*)d_out;

    float *pS, *pR;
    __nv_bfloat16 *pS0Ah, *pS0Al, *pS0Bh, *pS0Bl, *pAh, *pAl, *pM4h, *pM4l;
    cudaGetSymbolAddress((void**)&pS, g_S);
    cudaGetSymbolAddress((void**)&pR, g_R);
    cudaGetSymbolAddress((void**)&pS0Ah, g_S0Ah);
    cudaGetSymbolAddress((void**)&pS0Al, g_S0Al);
    cudaGetSymbolAddress((void**)&pS0Bh, g_S0Bh);
    cudaGetSymbolAddress((void**)&pS0Bl, g_S0Bl);
    cudaGetSymbolAddress((void**)&pAh, g_Ah);
    cudaGetSymbolAddress((void**)&pAl, g_Al);
    cudaGetSymbolAddress((void**)&pM4h, g_M4h);
    cudaGetSymbolAddress((void**)&pM4l, g_M4l);

    cudaFuncSetAttribute(mma_gemm, cudaFuncAttributeMaxDynamicSharedMemorySize, GSMEM);

    const int bigGrid = (PN * PN) / 256;

    for (int item = 0; item < 2; item++) {
        k_pack<<<(CC * PN + 255) / 256, 256>>>(f, b, item);
        k_stats<<<(PN + 255) / 256, 256>>>(mask, item);
        k_norm<<<(PN + 255) / 256, 256>>>();

        // S0[p][q] = sum_c Bd[c][p]*Fd[c][q]  (M=N=4096, K=128)
        mma_gemm<<<dim3(32, 32), 256, GSMEM>>>(pS0Ah, pS0Al, pS0Bh, pS0Bl, pS,
                                               PN, PN, CC);

        k_tap9<<<bigGrid, 256>>>();
        k_fuse1<<<bigGrid, 256>>>();
        k_fuse2<<<bigGrid, 256>>>();
        k_softmax<<<PN / 32, 256>>>();

        k_m4<<<dim3(KP / 256, KP), 256>>>();
        k_buildA<<<dim3(KP / 256, 512), 256>>>(b, item);

        // R[m][j] = sum_kp A[m][kp]*M4[kp][j]  (M=512, N=K=4352)
        mma_gemm<<<dim3(KP / 128, 4), 256, GSMEM>>>(pAh, pAl, pM4h, pM4l, pR,
                                                    512, KP, KP);

        k_out<<<(CC * HI * HI + 255) / 256, 256>>>(out, item);
    }
}

// round 5
// speedup vs baseline: 3.7415x; 1.0349x over previous
#include <cuda_runtime.h>
#include <cuda_bf16.h>
#include <math.h>
#include <stdint.h>

#define PN 4096            // 64*64 downsampled pixels/patches
#define CC 128
#define HI 128
#define KP 4352            // K padding of 65*65=4225
#define N2 4480            // N padding: 65 rows * 68 cols -> 35*128
#define NITEM 2

// ------------------------------------------------------ device scratch
__device__ __align__(128) float g_S[(size_t)NITEM * PN * PN];   // S0 -> F1
__device__ __align__(128) float g_T[(size_t)NITEM * PN * PN];   // T -> L -> e
__device__ __align__(128) float g_R[(size_t)NITEM * 512 * N2];
__device__ __align__(128) float g_Bd[NITEM * CC * PN];
__device__ float g_n2[NITEM * PN];
__device__ float g_inorm[NITEM * PN];
__device__ float g_mm[NITEM * PN];
__device__ float g_cmax[NITEM * PN];
__device__ float g_cinv[NITEM * PN];
__device__ __align__(128) __nv_bfloat16 g_S0Ah[NITEM * PN * CC];
__device__ __align__(128) __nv_bfloat16 g_S0Al[NITEM * PN * CC];
__device__ __align__(128) __nv_bfloat16 g_S0Bh[NITEM * CC * PN];
__device__ __align__(128) __nv_bfloat16 g_S0Bl[NITEM * CC * PN];
__device__ __align__(128) __nv_bfloat16 g_Ah[NITEM * 512 * KP];
__device__ __align__(128) __nv_bfloat16 g_Al[NITEM * 512 * KP];
__device__ __align__(128) __nv_bfloat16 g_M4h[(size_t)NITEM * KP * N2];
__device__ __align__(128) __nv_bfloat16 g_M4l[(size_t)NITEM * KP * N2];

// ------------------------------------------------------ PTX helpers
static __device__ __forceinline__ uint32_t smem_u32(const void* p) {
    uint32_t r;
    asm("{ .reg .u64 t; cvta.to.shared.u64 t, %1; cvt.u32.u64 %0, t; }" : "=r"(r) : "l"(p));
    return r;
}
#define CPA(s, g) asm volatile("cp.async.cg.shared.global [%0], [%1], 16;" :: "r"(s), "l"(g))
#define CPC() asm volatile("cp.async.commit_group;" ::: "memory")
#define CPW1() asm volatile("cp.async.wait_group 1;" ::: "memory")
#define LDSM4(R, a) \
    asm volatile("ldmatrix.sync.aligned.m8n8.x4.shared.b16 {%0,%1,%2,%3}, [%4];" \
        : "=r"((R)[0]), "=r"((R)[1]), "=r"((R)[2]), "=r"((R)[3]) : "r"(a))
#define LDSM4T(R, a) \
    asm volatile("ldmatrix.sync.aligned.m8n8.x4.trans.shared.b16 {%0,%1,%2,%3}, [%4];" \
        : "=r"((R)[0]), "=r"((R)[1]), "=r"((R)[2]), "=r"((R)[3]) : "r"(a))
#define MMA16816(D, A, B) \
    asm volatile("mma.sync.aligned.m16n8k16.row.col.f32.bf16.bf16.f32 " \
        "{%0,%1,%2,%3},{%4,%5,%6,%7},{%8,%9},{%0,%1,%2,%3};" \
        : "+f"((D)[0]), "+f"((D)[1]), "+f"((D)[2]), "+f"((D)[3]) \
        : "r"((A)[0]), "r"((A)[1]), "r"((A)[2]), "r"((A)[3]), "r"((B)[0]), "r"((B)[1]))

// ------------------------------------------------------ pack downsample
__global__ void k_pack(const float* __restrict__ f, const float* __restrict__ b) {
    int idx = blockIdx.x * blockDim.x + threadIdx.x;   // item*CC*PN + c*PN + q
    int item = idx >> 19;
    int c = (idx >> 12) & 127;
    int q = idx & 4095;
    int y = q >> 6, x = q & 63;
    size_t base = ((size_t)item * CC + c) * HI * HI + (size_t)(2 * y) * HI + 2 * x;
    float vf = f[base];
    float vb = b[base];
    g_Bd[idx] = vb;
    __nv_bfloat16 h = __float2bfloat16(vf);
    g_S0Bh[idx] = h;
    g_S0Bl[idx] = __float2bfloat16(vf - __bfloat162float(h));
    h = __float2bfloat16(vb);
    int o = (item << 19) + q * CC + c;
    g_S0Ah[o] = h;
    g_S0Al[o] = __float2bfloat16(vb - __bfloat162float(h));
}

__global__ void k_stats(const float* __restrict__ mask) {
    int p = blockIdx.x * blockDim.x + threadIdx.x;
    int item = blockIdx.y;
    const float* Bd = g_Bd + item * CC * PN;
    float s = 0.f;
    for (int c = 0; c < CC; c++) {
        float v = Bd[c * PN + p];
        s += v * v;
    }
    g_n2[item * PN + p] = s;
    int ph = p >> 6, pw = p & 63;
    const float* m = mask + (size_t)item * HI * HI;
    float ms = 0.f;
    for (int dh = -1; dh <= 1; dh++)
        for (int dw = -1; dw <= 1; dw++) {
            int yy = ph + dh, xx = pw + dw;
            if ((unsigned)yy < 64u && (unsigned)xx < 64u)
                ms += m[(2 * yy) * HI + 2 * xx];
        }
    g_mm[item * PN + p] = (ms / 9.0f == 0.0f) ? 1.0f : 0.0f;
}

__global__ void k_norm() {
    int p = blockIdx.x * blockDim.x + threadIdx.x;
    int item = blockIdx.y;
    int ph = p >> 6, pw = p & 63;
    float s = 0.f;
    for (int dh = -1; dh <= 1; dh++)
        for (int dw = -1; dw <= 1; dw++) {
            int yy = ph + dh, xx = pw + dw;
            if ((unsigned)yy < 64u && (unsigned)xx < 64u)
                s += g_n2[item * PN + yy * 64 + xx];
        }
    g_inorm[item * PN + p] = rsqrtf(s + 0.1152f);
}

// =================================================== split-bf16 MMA GEMM
// C[M][N] = sum_k (Ah+Al)[m][k]*(Bh+Bl)[k][n]; CTA 128x128, 3-stage cp.async
#define SA 10240      // 128 rows * 40 bf16 * 2B
#define SBZ 8704      // 32 rows * 136 bf16 * 2B
#define GSMEM (6 * SA + 6 * SBZ)   // 113664

__global__ void __launch_bounds__(256) mma_gemm(
    const __nv_bfloat16* __restrict__ Ah, const __nv_bfloat16* __restrict__ Al,
    const __nv_bfloat16* __restrict__ Bh, const __nv_bfloat16* __restrict__ Bl,
    float* __restrict__ C, int M, int N, int K,
    size_t sA, size_t sB, size_t sC) {
    extern __shared__ char smem[];
    uint32_t sb = smem_u32(smem);
    int tid = threadIdx.x;
    int lane = tid & 31, wid = tid >> 5;
    int warpM = wid >> 1, warpN = wid & 1;
    int m0 = blockIdx.y * 128, n0 = blockIdx.x * 128;
    int item = blockIdx.z;
    Ah += item * sA; Al += item * sA;
    Bh += item * sB; Bl += item * sB;
    C += item * sC;

    float acc[2][8][4];
#pragma unroll
    for (int i = 0; i < 2; i++)
#pragma unroll
        for (int j = 0; j < 8; j++)
#pragma unroll
            for (int v = 0; v < 4; v++) acc[i][j][v] = 0.f;

    auto load_stage = [&](int st, int kc) {
#pragma unroll
        for (int ma = 0; ma < 2; ma++) {
            const __nv_bfloat16* src = ma ? Al : Ah;
            uint32_t sbase = sb + (ma * 3 + st) * SA;
#pragma unroll
            for (int it = 0; it < 2; it++) {
                int idx = it * 256 + tid;
                int row = idx >> 2, seg = idx & 3;
                const void* g = src + (size_t)(m0 + row) * K + kc + seg * 8;
                CPA(sbase + (row * 40 + seg * 8) * 2, g);
            }
        }
#pragma unroll
        for (int mb = 0; mb < 2; mb++) {
            const __nv_bfloat16* src = mb ? Bl : Bh;
            uint32_t sbase = sb + 6 * SA + (mb * 3 + st) * SBZ;
#pragma unroll
            for (int it = 0; it < 2; it++) {
                int idx = it * 256 + tid;
                int row = idx >> 4, seg = idx & 15;
                const void* g = src + (size_t)(kc + row) * N + n0 + seg * 8;
                CPA(sbase + (row * 136 + seg * 8) * 2, g);
            }
        }
        CPC();
    };

    load_stage(0, 0);
    load_stage(1, 32);
    int NC = K >> 5;
    for (int c = 0; c < NC; c++) {
        CPW1();
        __syncthreads();
        int nc = c + 2;
        if (nc < NC) {
            int sidx = nc % 3;
            load_stage(sidx, nc << 5);
        } else {
            CPC();
        }
        int st = c % 3;
        uint32_t baseAh = sb + st * SA;
        uint32_t baseAl = sb + (3 + st) * SA;
        uint32_t baseBh = sb + 6 * SA + st * SBZ;
        uint32_t baseBl = sb + 6 * SA + (3 + st) * SBZ;
#pragma unroll
        for (int kk = 0; kk < 2; kk++) {
            uint32_t ah[2][4], al[2][4], bh[4][4], bl[4][4];
#pragma unroll
            for (int mb = 0; mb < 2; mb++) {
                uint32_t a = ((warpM * 32 + mb * 16 + (lane & 15)) * 40 + kk * 16 + (lane >> 4) * 8) * 2;
                LDSM4(ah[mb], baseAh + a);
                LDSM4(al[mb], baseAl + a);
            }
#pragma unroll
            for (int nb = 0; nb < 4; nb++) {
                uint32_t a = ((kk * 16 + (lane & 15)) * 136 + warpN * 64 + nb * 16 + (lane >> 4) * 8) * 2;
                LDSM4T(bh[nb], baseBh + a);
                LDSM4T(bl[nb], baseBl + a);
            }
#pragma unroll
            for (int mb = 0; mb < 2; mb++)
#pragma unroll
                for (int nb = 0; nb < 4; nb++)
#pragma unroll
                    for (int h = 0; h < 2; h++) {
                        float* D = acc[mb][nb * 2 + h];
                        MMA16816(D, ah[mb], &bh[nb][h * 2]);
                        MMA16816(D, ah[mb], &bl[nb][h * 2]);
                        MMA16816(D, al[mb], &bh[nb][h * 2]);
                    }
        }
    }
    int g = lane >> 2, tg = lane & 3;
#pragma unroll
    for (int mb = 0; mb < 2; mb++)
#pragma unroll
        for (int j = 0; j < 8; j++) {
            int row = m0 + warpM * 32 + mb * 16 + g;
            int col = n0 + warpN * 64 + j * 8 + tg * 2;
            float2 v0 = make_float2(acc[mb][j][0], acc[mb][j][1]);
            float2 v1 = make_float2(acc[mb][j][2], acc[mb][j][3]);
            *(float2*)&C[(size_t)row * N + col] = v0;
            *(float2*)&C[(size_t)(row + 8) * N + col] = v1;
        }
}

// ------------------------ vectorized 9-tap diagonal gather + normalize
// T[p][q] = inorm[p] * sum_{dh,dw valid} S0[p + dh*64 + dw][q + dh*64 + dw]
// dw=+-1 taps live at rows a+-PN shifted one column (offset +-(PN+1)).
__global__ __launch_bounds__(256) void k_tap9v() {
    int vid = blockIdx.x * 256 + threadIdx.x;     // element/4 id
    int item = blockIdx.y;
    int p = vid >> 10;
    int q0 = (vid & 1023) << 2;
    int ph = p >> 6, pw = p & 63, qh = q0 >> 6, qw0 = q0 & 63;
    const float* S = g_S + (size_t)item * PN * PN;
    float4 acc = make_float4(0.f, 0.f, 0.f, 0.f);
    bool pm = (pw >= 1), pp_ = (pw <= 62);
#pragma unroll
    for (int dh = -1; dh <= 1; dh++) {
        if ((unsigned)(ph + dh) >= 64u || (unsigned)(qh + dh) >= 64u) continue;
        size_t a = (size_t)p * PN + q0 + (size_t)((long)dh * (64 * PN + 64));
        float4 Cv = *(const float4*)&S[a];
        acc.x += Cv.x; acc.y += Cv.y; acc.z += Cv.z; acc.w += Cv.w;
        if (pm) {   // dw = -1: row pw-1, columns q0-1..q0+2
            float4 Mv = *(const float4*)&S[a - PN];
            float ml = (qw0 >= 1) ? S[a - PN - 1] : 0.f;
            acc.x += ml; acc.y += Mv.x; acc.z += Mv.y; acc.w += Mv.z;
        }
        if (pp_) {  // dw = +1: row pw+1, columns q0+1..q0+4
            float4 Pv = *(const float4*)&S[a + PN];
            float pr = (qw0 <= 59) ? S[a + PN + 4] : 0.f;
            acc.x += Pv.y; acc.y += Pv.z; acc.z += Pv.w; acc.w += pr;
        }
    }
    float in_ = g_inorm[item * PN + p];
    acc.x *= in_; acc.y *= in_; acc.z *= in_; acc.w *= in_;
    *(float4*)&g_T[(size_t)item * PN * PN + (size_t)p * PN + q0] = acc;
}

// ------------------------ vectorized fuse pass 1 (flat diagonal 3-tap)
// F1[r][c] = T[r-1][c-1] + T[r][c] + T[r+1][c+1]
__global__ __launch_bounds__(256) void k_fuse1v() {
    int vid = blockIdx.x * 256 + threadIdx.x;
    int item = blockIdx.y;
    int r = vid >> 10;
    int c0 = (vid & 1023) << 2;
    const float* T = g_T + (size_t)item * PN * PN;
    size_t idx4 = (size_t)r * PN + c0;
    float4 res = *(const float4*)&T[idx4];
    if (r >= 1) {
        float4 U = *(const float4*)&T[idx4 - PN];
        float lu = (c0 >= 1) ? T[idx4 - PN - 1] : 0.f;
        res.x += lu; res.y += U.x; res.z += U.y; res.w += U.z;
    }
    if (r <= PN - 2) {
        float4 D = *(const float4*)&T[idx4 + PN];
        float rd = (c0 <= PN - 5) ? T[idx4 + PN + 4] : 0.f;
        res.x += D.y; res.y += D.z; res.z += D.w; res.w += rd;
    }
    *(float4*)&g_S[(size_t)item * PN * PN + idx4] = res;
}

// ---------------- fuse2 + column max: L[p][q] = 10*mm[p]*Z[p][q], colmax
__global__ __launch_bounds__(256) void k_fz() {
    int lane = threadIdx.x & 31, r = threadIdx.x >> 5;
    int q = blockIdx.x * 32 + lane;
    int item = blockIdx.y;
    const float* F1 = g_S + (size_t)item * PN * PN;
    float* L = g_T + (size_t)item * PN * PN;
    const float* mm = g_mm + item * PN;
    const long D = 64L * (PN + 1);
    bool qIn = (q >= 64 && q < PN - 64);
    int rq = (q & 63) * 64 + (q >> 6);
    float mx = -1e30f;
    for (int p = r; p < PN; p += 8) {
        float s;
        if (qIn && p >= 64 && p < PN - 64) {
            size_t idx = (size_t)p * PN + q;
            s = F1[idx - D] + F1[idx] + F1[idx + D];
        } else {
            int rp = (p & 63) * 64 + (p >> 6);
            s = 0.f;
#pragma unroll
            for (int j = -1; j <= 1; j++) {
                int tp = rp + j, tq = rq + j;
                if ((unsigned)tp < (unsigned)PN && (unsigned)tq < (unsigned)PN) {
                    int pp = (tp & 63) * 64 + (tp >> 6);
                    int qq = (tq & 63) * 64 + (tq >> 6);
                    s += F1[(size_t)pp * PN + qq];
                }
            }
        }
        float l = 10.f * s * mm[p];
        L[(size_t)p * PN + q] = l;
        mx = fmaxf(mx, l);
    }
    __shared__ float red[8][32];
    red[r][lane] = mx;
    __syncthreads();
    if (threadIdx.x < 32) {
        float m = red[0][threadIdx.x];
#pragma unroll
        for (int i = 1; i < 8; i++) m = fmaxf(m, red[i][threadIdx.x]);
        g_cmax[item * PN + blockIdx.x * 32 + threadIdx.x] = m;
    }
}

// ---------------- exp once (with skip), column sum -> inv; store e*mm
__global__ __launch_bounds__(256) void k_esum() {
    int lane = threadIdx.x & 31, r = threadIdx.x >> 5;
    int q = blockIdx.x * 32 + lane;
    int item = blockIdx.y;
    float* L = g_T + (size_t)item * PN * PN;
    const float* mm = g_mm + item * PN;
    float mx = g_cmax[item * PN + q];
    float s = 0.f;
    for (int p = r; p < PN; p += 8) {
        float d = L[(size_t)p * PN + q] - mx;
        float e = (d > -25.f) ? __expf(d) : 0.f;
        s += e;
        L[(size_t)p * PN + q] = e * mm[p];
    }
    __shared__ float red[8][32];
    red[r][lane] = s;
    __syncthreads();
    if (threadIdx.x < 32) {
        float t = red[0][threadIdx.x];
#pragma unroll
        for (int i = 1; i < 8; i++) t += red[i][threadIdx.x];
        g_cinv[item * PN + blockIdx.x * 32 + threadIdx.x] = 1.f / t;
    }
}

// ---------------- M4 blur with folded normalization:
// M4[p'][Y0*68+X0] = sum_{a,b} e[(ph-a)*64+pw-b][(Y0-a)*64+X0-b]*inv[(Y0-a)*64+X0-b]
#define M4W (65 * 17)   // (Y0, chunk) pairs per p'
__global__ __launch_bounds__(256) void k_m4() {
    int id = blockIdx.x * 256 + threadIdx.x;
    int item = blockIdx.y;
    if (id >= 4225 * M4W) return;
    int pp = id / M4W;
    int rem = id - pp * M4W;
    int Y0 = rem / 17;
    int k = rem - Y0 * 17;
    int ph = pp / 65, pw = pp - ph * 65;
    const float* E = g_T + (size_t)item * PN * PN;
    const float* inv = g_cinv + item * PN;
    size_t jb = (size_t)item * KP * N2 + (size_t)pp * N2 + Y0 * 68 + 4 * k;

    float4 acc = make_float4(0.f, 0.f, 0.f, 0.f);
    if (k < 16) {
#pragma unroll
        for (int a = 0; a < 2; a++) {
            int ya = Y0 - a, pa = ph - a;
            if ((unsigned)ya >= 64u || (unsigned)pa >= 64u) continue;
            int ib = ya * 64 + 4 * k;
            if (pw <= 63) {
                const float* rowE = E + (size_t)(pa * 64 + pw) * PN;
                float4 ev = *(const float4*)&rowE[ib];
                float4 iv = *(const float4*)&inv[ib];
                acc.x += ev.x * iv.x; acc.y += ev.y * iv.y;
                acc.z += ev.z * iv.z; acc.w += ev.w * iv.w;
            }
            if (pw >= 1) {
                const float* rowE = E + (size_t)(pa * 64 + pw - 1) * PN;
                float4 ev = *(const float4*)&rowE[ib];
                float4 iv = *(const float4*)&inv[ib];
                float le = (k >= 1) ? rowE[ib - 1] : 0.f;
                float li = (k >= 1) ? inv[ib - 1] : 0.f;
                acc.x += le * li;
                acc.y += ev.x * iv.x; acc.z += ev.y * iv.y; acc.w += ev.z * iv.z;
            }
        }
    } else {
        // X0 = 64 tail: only b=1 taps; also zero-fill pad cols 65..67
        float v = 0.f;
        if (pw >= 1) {
#pragma unroll
            for (int a = 0; a < 2; a++) {
                int ya = Y0 - a, pa = ph - a;
                if ((unsigned)ya >= 64u || (unsigned)pa >= 64u) continue;
                int ib = ya * 64 + 63;
                v += E[(size_t)(pa * 64 + pw - 1) * PN + ib] * inv[ib];
            }
        }
        acc.x = v;
    }
    __nv_bfloat16 h0 = __float2bfloat16(acc.x);
    __nv_bfloat16 h1 = __float2bfloat16(acc.y);
    __nv_bfloat16 h2 = __float2bfloat16(acc.z);
    __nv_bfloat16 h3 = __float2bfloat16(acc.w);
    __nv_bfloat16 hv[4] = {h0, h1, h2, h3};
    __nv_bfloat16 lv[4] = {
        __float2bfloat16(acc.x - __bfloat162float(h0)),
        __float2bfloat16(acc.y - __bfloat162float(h1)),
        __float2bfloat16(acc.z - __bfloat162float(h2)),
        __float2bfloat16(acc.w - __bfloat162float(h3))};
    *(uint2*)&g_M4h[jb] = *(uint2*)hv;
    *(uint2*)&g_M4l[jb] = *(uint2*)lv;
}

// ---------------- A for deconv GEMM: A[(cls,c)][kp] = b tap
__global__ void k_buildA(const float* __restrict__ b) {
    int m = blockIdx.y;
    int kp = blockIdx.x * 256 + threadIdx.x;
    int item = blockIdx.z;
    size_t o = (size_t)item * 512 * KP + (size_t)m * KP + kp;
    float v = 0.f;
    if (kp < 4225) {
        int cls = m >> 7, c = m & 127;
        int pky = cls >> 1, pkx = cls & 1;
        int ph = kp / 65, pw = kp % 65;
        int Y = 2 * ph - 1 + pky;
        int X = 2 * pw - 1 + pkx;
        if ((unsigned)Y < 128u && (unsigned)X < 128u)
            v = b[(((size_t)item * CC + c) * HI + Y) * HI + X];
    }
    __nv_bfloat16 h = __float2bfloat16(v);
    g_Ah[o] = h;
    g_Al[o] = __float2bfloat16(v - __bfloat162float(h));
}

// ---------------- trivial gather
__global__ void k_out(float* __restrict__ out) {
    int idx = blockIdx.x * 256 + threadIdx.x;   // item*2^21 + c*2^14 + Y*128 + X
    int item = idx >> 21;
    int c = (idx >> 14) & 127;
    int Y = (idx >> 7) & 127, X = idx & 127;
    int pky = (Y + 1) & 1, pkx = (X + 1) & 1;
    int Y0 = (Y + 1) >> 1, X0 = (X + 1) >> 1;
    int cls = pky * 2 + pkx;
    out[idx] = 0.25f * g_R[(size_t)item * 512 * N2 +
                           (size_t)(cls * 128 + c) * N2 + Y0 * 68 + X0];
}

// ---------------------------------------------------------------- launcher
extern "C" void kernel_launch(void* const* d_in, const int* in_sizes, int n_in,
                              void* d_out, int out_size) {
    const float* f = (const float*)d_in[0];
    const float* b = (const float*)d_in[1];
    const float* mask = (const float*)d_in[2];
    float* out = (float*)d_out;

    float *pS, *pR;
    __nv_bfloat16 *pS0Ah, *pS0Al, *pS0Bh, *pS0Bl, *pAh, *pAl, *pM4h, *pM4l;
    cudaGetSymbolAddress((void**)&pS, g_S);
    cudaGetSymbolAddress((void**)&pR, g_R);
    cudaGetSymbolAddress((void**)&pS0Ah, g_S0Ah);
    cudaGetSymbolAddress((void**)&pS0Al, g_S0Al);
    cudaGetSymbolAddress((void**)&pS0Bh, g_S0Bh);
    cudaGetSymbolAddress((void**)&pS0Bl, g_S0Bl);
    cudaGetSymbolAddress((void**)&pAh, g_Ah);
    cudaGetSymbolAddress((void**)&pAl, g_Al);
    cudaGetSymbolAddress((void**)&pM4h, g_M4h);
    cudaGetSymbolAddress((void**)&pM4l, g_M4l);

    cudaFuncSetAttribute(mma_gemm, cudaFuncAttributeMaxDynamicSharedMemorySize, GSMEM);

    k_pack<<<(NITEM * CC * PN) / 256, 256>>>(f, b);
    k_stats<<<dim3(PN / 256, NITEM), 256>>>(mask);
    k_norm<<<dim3(PN / 256, NITEM), 256>>>();

    // S0[p][q] = sum_c Bd[c][p]*Fd[c][q]  (M=N=4096, K=128)
    mma_gemm<<<dim3(32, 32, NITEM), 256, GSMEM>>>(
        pS0Ah, pS0Al, pS0Bh, pS0Bl, pS, PN, PN, CC,
        (size_t)PN * CC, (size_t)CC * PN, (size_t)PN * PN);

    k_tap9v<<<dim3(PN * PN / 1024, NITEM), 256>>>();
    k_fuse1v<<<dim3(PN * PN / 1024, NITEM), 256>>>();
    k_fz<<<dim3(PN / 32, NITEM), 256>>>();
    k_esum<<<dim3(PN / 32, NITEM), 256>>>();

    k_m4<<<dim3((4225 * M4W + 255) / 256, NITEM), 256>>>();
    k_buildA<<<dim3(KP / 256, 512, NITEM), 256>>>(b);

    // R[m][j] = sum_kp A[m][kp]*M4[kp][j]  (M=512, N=4480, K=4352)
    mma_gemm<<<dim3(N2 / 128, 4, NITEM), 256, GSMEM>>>(
        pAh, pAl, pM4h, pM4l, pR, 512, N2, KP,
        (size_t)512 * KP, (size_t)KP * N2, (size_t)512 * N2);

    k_out<<<(NITEM * CC * HI * HI) / 256, 256>>>(out);
}

// round 6
// speedup vs baseline: 5.6860x; 1.5197x over previous
#include <cuda_runtime.h>
#include <cuda_bf16.h>
#include <math.h>
#include <stdint.h>

#define PN 4096            // 64*64 downsampled pixels/patches
#define CC 128
#define HI 128
#define NITEM 2

// ------------------------------------------------------ device scratch
__device__ __align__(128) float g_S[(size_t)NITEM * PN * PN];   // S0 -> F1
__device__ __align__(128) float g_T[(size_t)NITEM * PN * PN];   // T -> Lt
__device__ __align__(128) float g_Bd[NITEM * CC * PN];
__device__ float g_n2[NITEM * PN];
__device__ float g_inorm[NITEM * PN];
__device__ float g_mm[NITEM * PN];
__device__ float g_cmax[NITEM * PN];
__device__ float g_cinv[NITEM * PN];
__device__ int   g_nnz[NITEM * PN];
__device__ __align__(128) short g_sp[(size_t)NITEM * PN * PN];  // sparse p idx
__device__ __align__(128) float g_se[(size_t)NITEM * PN * PN];  // sparse e*mm
__device__ __align__(128) float g_btr[NITEM * HI * HI * CC];    // b^T [yx][c]
__device__ __align__(128) float g_O[NITEM * HI * HI * CC];      // out^T [yx][c]
__device__ __align__(128) __nv_bfloat16 g_S0Ah[NITEM * PN * CC];
__device__ __align__(128) __nv_bfloat16 g_S0Al[NITEM * PN * CC];
__device__ __align__(128) __nv_bfloat16 g_S0Bh[NITEM * CC * PN];
__device__ __align__(128) __nv_bfloat16 g_S0Bl[NITEM * CC * PN];

// ------------------------------------------------------ PTX helpers
static __device__ __forceinline__ uint32_t smem_u32(const void* p) {
    uint32_t r;
    asm("{ .reg .u64 t; cvta.to.shared.u64 t, %1; cvt.u32.u64 %0, t; }" : "=r"(r) : "l"(p));
    return r;
}
#define CPA(s, g) asm volatile("cp.async.cg.shared.global [%0], [%1], 16;" :: "r"(s), "l"(g))
#define CPC() asm volatile("cp.async.commit_group;" ::: "memory")
#define CPW1() asm volatile("cp.async.wait_group 1;" ::: "memory")
#define LDSM4(R, a) \
    asm volatile("ldmatrix.sync.aligned.m8n8.x4.shared.b16 {%0,%1,%2,%3}, [%4];" \
        : "=r"((R)[0]), "=r"((R)[1]), "=r"((R)[2]), "=r"((R)[3]) : "r"(a))
#define LDSM4T(R, a) \
    asm volatile("ldmatrix.sync.aligned.m8n8.x4.trans.shared.b16 {%0,%1,%2,%3}, [%4];" \
        : "=r"((R)[0]), "=r"((R)[1]), "=r"((R)[2]), "=r"((R)[3]) : "r"(a))
#define MMA16816(D, A, B) \
    asm volatile("mma.sync.aligned.m16n8k16.row.col.f32.bf16.bf16.f32 " \
        "{%0,%1,%2,%3},{%4,%5,%6,%7},{%8,%9},{%0,%1,%2,%3};" \
        : "+f"((D)[0]), "+f"((D)[1]), "+f"((D)[2]), "+f"((D)[3]) \
        : "r"((A)[0]), "r"((A)[1]), "r"((A)[2]), "r"((A)[3]), "r"((B)[0]), "r"((B)[1]))

// ------------------------------------------------------ pack downsample
__global__ void k_pack(const float* __restrict__ f, const float* __restrict__ b) {
    int idx = blockIdx.x * blockDim.x + threadIdx.x;   // item*CC*PN + c*PN + q
    int item = idx >> 19;
    int c = (idx >> 12) & 127;
    int q = idx & 4095;
    int y = q >> 6, x = q & 63;
    size_t base = ((size_t)item * CC + c) * HI * HI + (size_t)(2 * y) * HI + 2 * x;
    float vf = f[base];
    float vb = b[base];
    g_Bd[idx] = vb;
    __nv_bfloat16 h = __float2bfloat16(vf);
    g_S0Bh[idx] = h;
    g_S0Bl[idx] = __float2bfloat16(vf - __bfloat162float(h));
    h = __float2bfloat16(vb);
    int o = (item << 19) + q * CC + c;
    g_S0Ah[o] = h;
    g_S0Al[o] = __float2bfloat16(vb - __bfloat162float(h));
}

__global__ void k_stats(const float* __restrict__ mask) {
    int p = blockIdx.x * blockDim.x + threadIdx.x;
    int item = blockIdx.y;
    const float* Bd = g_Bd + item * CC * PN;
    float s = 0.f;
    for (int c = 0; c < CC; c++) {
        float v = Bd[c * PN + p];
        s += v * v;
    }
    g_n2[item * PN + p] = s;
    int ph = p >> 6, pw = p & 63;
    const float* m = mask + (size_t)item * HI * HI;
    float ms = 0.f;
    for (int dh = -1; dh <= 1; dh++)
        for (int dw = -1; dw <= 1; dw++) {
            int yy = ph + dh, xx = pw + dw;
            if ((unsigned)yy < 64u && (unsigned)xx < 64u)
                ms += m[(2 * yy) * HI + 2 * xx];
        }
    g_mm[item * PN + p] = (ms / 9.0f == 0.0f) ? 1.0f : 0.0f;
}

__global__ void k_norm() {
    int p = blockIdx.x * blockDim.x + threadIdx.x;
    int item = blockIdx.y;
    int ph = p >> 6, pw = p & 63;
    float s = 0.f;
    for (int dh = -1; dh <= 1; dh++)
        for (int dw = -1; dw <= 1; dw++) {
            int yy = ph + dh, xx = pw + dw;
            if ((unsigned)yy < 64u && (unsigned)xx < 64u)
                s += g_n2[item * PN + yy * 64 + xx];
        }
    g_inorm[item * PN + p] = rsqrtf(s + 0.1152f);
}

// =================================================== split-bf16 MMA GEMM (S0)
#define SA 10240      // 128 rows * 40 bf16 * 2B
#define SBZ 8704      // 32 rows * 136 bf16 * 2B
#define GSMEM (6 * SA + 6 * SBZ)   // 113664

__global__ void __launch_bounds__(256) mma_gemm(
    const __nv_bfloat16* __restrict__ Ah, const __nv_bfloat16* __restrict__ Al,
    const __nv_bfloat16* __restrict__ Bh, const __nv_bfloat16* __restrict__ Bl,
    float* __restrict__ C, int M, int N, int K,
    size_t sA, size_t sB, size_t sC) {
    extern __shared__ char smem[];
    uint32_t sb = smem_u32(smem);
    int tid = threadIdx.x;
    int lane = tid & 31, wid = tid >> 5;
    int warpM = wid >> 1, warpN = wid & 1;
    int m0 = blockIdx.y * 128, n0 = blockIdx.x * 128;
    int item = blockIdx.z;
    Ah += item * sA; Al += item * sA;
    Bh += item * sB; Bl += item * sB;
    C += item * sC;

    float acc[2][8][4];
#pragma unroll
    for (int i = 0; i < 2; i++)
#pragma unroll
        for (int j = 0; j < 8; j++)
#pragma unroll
            for (int v = 0; v < 4; v++) acc[i][j][v] = 0.f;

    auto load_stage = [&](int st, int kc) {
#pragma unroll
        for (int ma = 0; ma < 2; ma++) {
            const __nv_bfloat16* src = ma ? Al : Ah;
            uint32_t sbase = sb + (ma * 3 + st) * SA;
#pragma unroll
            for (int it = 0; it < 2; it++) {
                int idx = it * 256 + tid;
                int row = idx >> 2, seg = idx & 3;
                const void* g = src + (size_t)(m0 + row) * K + kc + seg * 8;
                CPA(sbase + (row * 40 + seg * 8) * 2, g);
            }
        }
#pragma unroll
        for (int mb = 0; mb < 2; mb++) {
            const __nv_bfloat16* src = mb ? Bl : Bh;
            uint32_t sbase = sb + 6 * SA + (mb * 3 + st) * SBZ;
#pragma unroll
            for (int it = 0; it < 2; it++) {
                int idx = it * 256 + tid;
                int row = idx >> 4, seg = idx & 15;
                const void* g = src + (size_t)(kc + row) * N + n0 + seg * 8;
                CPA(sbase + (row * 136 + seg * 8) * 2, g);
            }
        }
        CPC();
    };

    load_stage(0, 0);
    load_stage(1, 32);
    int NC = K >> 5;
    for (int c = 0; c < NC; c++) {
        CPW1();
        __syncthreads();
        int nc = c + 2;
        if (nc < NC) {
            int sidx = nc % 3;
            load_stage(sidx, nc << 5);
        } else {
            CPC();
        }
        int st = c % 3;
        uint32_t baseAh = sb + st * SA;
        uint32_t baseAl = sb + (3 + st) * SA;
        uint32_t baseBh = sb + 6 * SA + st * SBZ;
        uint32_t baseBl = sb + 6 * SA + (3 + st) * SBZ;
#pragma unroll
        for (int kk = 0; kk < 2; kk++) {
            uint32_t ah[2][4], al[2][4], bh[4][4], bl[4][4];
#pragma unroll
            for (int mb = 0; mb < 2; mb++) {
                uint32_t a = ((warpM * 32 + mb * 16 + (lane & 15)) * 40 + kk * 16 + (lane >> 4) * 8) * 2;
                LDSM4(ah[mb], baseAh + a);
                LDSM4(al[mb], baseAl + a);
            }
#pragma unroll
            for (int nb = 0; nb < 4; nb++) {
                uint32_t a = ((kk * 16 + (lane & 15)) * 136 + warpN * 64 + nb * 16 + (lane >> 4) * 8) * 2;
                LDSM4T(bh[nb], baseBh + a);
                LDSM4T(bl[nb], baseBl + a);
            }
#pragma unroll
            for (int mb = 0; mb < 2; mb++)
#pragma unroll
                for (int nb = 0; nb < 4; nb++)
#pragma unroll
                    for (int h = 0; h < 2; h++) {
                        float* D = acc[mb][nb * 2 + h];
                        MMA16816(D, ah[mb], &bh[nb][h * 2]);
                        MMA16816(D, ah[mb], &bl[nb][h * 2]);
                        MMA16816(D, al[mb], &bh[nb][h * 2]);
                    }
        }
    }
    int g = lane >> 2, tg = lane & 3;
#pragma unroll
    for (int mb = 0; mb < 2; mb++)
#pragma unroll
        for (int j = 0; j < 8; j++) {
            int row = m0 + warpM * 32 + mb * 16 + g;
            int col = n0 + warpN * 64 + j * 8 + tg * 2;
            float2 v0 = make_float2(acc[mb][j][0], acc[mb][j][1]);
            float2 v1 = make_float2(acc[mb][j][2], acc[mb][j][3]);
            *(float2*)&C[(size_t)row * N + col] = v0;
            *(float2*)&C[(size_t)(row + 8) * N + col] = v1;
        }
}

// ------------------------ vectorized 9-tap diagonal gather + normalize
__global__ __launch_bounds__(256) void k_tap9v() {
    int vid = blockIdx.x * 256 + threadIdx.x;
    int item = blockIdx.y;
    int p = vid >> 10;
    int q0 = (vid & 1023) << 2;
    int ph = p >> 6, pw = p & 63, qh = q0 >> 6, qw0 = q0 & 63;
    const float* S = g_S + (size_t)item * PN * PN;
    float4 acc = make_float4(0.f, 0.f, 0.f, 0.f);
    bool pm = (pw >= 1), pp_ = (pw <= 62);
#pragma unroll
    for (int dh = -1; dh <= 1; dh++) {
        if ((unsigned)(ph + dh) >= 64u || (unsigned)(qh + dh) >= 64u) continue;
        size_t a = (size_t)p * PN + q0 + (size_t)((long)dh * (64 * PN + 64));
        float4 Cv = *(const float4*)&S[a];
        acc.x += Cv.x; acc.y += Cv.y; acc.z += Cv.z; acc.w += Cv.w;
        if (pm) {
            float4 Mv = *(const float4*)&S[a - PN];
            float ml = (qw0 >= 1) ? S[a - PN - 1] : 0.f;
            acc.x += ml; acc.y += Mv.x; acc.z += Mv.y; acc.w += Mv.z;
        }
        if (pp_) {
            float4 Pv = *(const float4*)&S[a + PN];
            float pr = (qw0 <= 59) ? S[a + PN + 4] : 0.f;
            acc.x += Pv.y; acc.y += Pv.z; acc.z += Pv.w; acc.w += pr;
        }
    }
    float in_ = g_inorm[item * PN + p];
    acc.x *= in_; acc.y *= in_; acc.z *= in_; acc.w *= in_;
    *(float4*)&g_T[(size_t)item * PN * PN + (size_t)p * PN + q0] = acc;
}

// ------------------------ vectorized fuse pass 1 (flat diagonal 3-tap)
__global__ __launch_bounds__(256) void k_fuse1v() {
    int vid = blockIdx.x * 256 + threadIdx.x;
    int item = blockIdx.y;
    int r = vid >> 10;
    int c0 = (vid & 1023) << 2;
    const float* T = g_T + (size_t)item * PN * PN;
    size_t idx4 = (size_t)r * PN + c0;
    float4 res = *(const float4*)&T[idx4];
    if (r >= 1) {
        float4 U = *(const float4*)&T[idx4 - PN];
        float lu = (c0 >= 1) ? T[idx4 - PN - 1] : 0.f;
        res.x += lu; res.y += U.x; res.z += U.y; res.w += U.z;
    }
    if (r <= PN - 2) {
        float4 D = *(const float4*)&T[idx4 + PN];
        float rd = (c0 <= PN - 5) ? T[idx4 + PN + 4] : 0.f;
        res.x += D.y; res.y += D.z; res.z += D.w; res.w += rd;
    }
    *(float4*)&g_S[(size_t)item * PN * PN + idx4] = res;
}

// ---------------- fuse2 + column max; writes logits TRANSPOSED Lt[q][p]
__global__ __launch_bounds__(256) void k_fz() {
    int lane = threadIdx.x & 31, r = threadIdx.x >> 5;
    int q0 = blockIdx.x * 32;
    int q = q0 + lane;
    int item = blockIdx.y;
    const float* F1 = g_S + (size_t)item * PN * PN;
    float* Lt = g_T + (size_t)item * PN * PN;
    const float* mm = g_mm + item * PN;
    const long D = 64L * (PN + 1);
    bool qIn = (q >= 64 && q < PN - 64);
    int rq = (q & 63) * 64 + (q >> 6);
    float mx = -1e30f;
    __shared__ float tile[32][33];
    __shared__ float red[8][32];

    for (int pt = 0; pt < PN; pt += 32) {
#pragma unroll
        for (int s4 = 0; s4 < 4; s4++) {
            int p = pt + s4 * 8 + r;
            float s;
            if (qIn && p >= 64 && p < PN - 64) {
                size_t idx = (size_t)p * PN + q;
                s = F1[idx - D] + F1[idx] + F1[idx + D];
            } else {
                int rp = (p & 63) * 64 + (p >> 6);
                s = 0.f;
#pragma unroll
                for (int j = -1; j <= 1; j++) {
                    int tp = rp + j, tq = rq + j;
                    if ((unsigned)tp < (unsigned)PN && (unsigned)tq < (unsigned)PN) {
                        int pp = (tp & 63) * 64 + (tp >> 6);
                        int qq = (tq & 63) * 64 + (tq >> 6);
                        s += F1[(size_t)pp * PN + qq];
                    }
                }
            }
            float l = 10.f * s * mm[p];
            tile[s4 * 8 + r][lane] = l;
            mx = fmaxf(mx, l);
        }
        __syncthreads();
#pragma unroll
        for (int k = 0; k < 4; k++) {
            int qq = r * 4 + k;
            Lt[(size_t)(q0 + qq) * PN + pt + lane] = tile[lane][qq];
        }
        __syncthreads();
    }
    red[r][lane] = mx;
    __syncthreads();
    if (threadIdx.x < 32) {
        float m = red[0][threadIdx.x];
#pragma unroll
        for (int i = 1; i < 8; i++) m = fmaxf(m, red[i][threadIdx.x]);
        g_cmax[item * PN + q0 + threadIdx.x] = m;
    }
}

// ---------------- exp + sum + sparse compaction (warp per column q)
__global__ __launch_bounds__(256) void k_esum() {
    int lane = threadIdx.x & 31, wid = threadIdx.x >> 5;
    int q = blockIdx.x * 8 + wid;
    int item = blockIdx.y;
    const float* Lt = g_T + (size_t)item * PN * PN + (size_t)q * PN;
    const float* mm = g_mm + item * PN;
    float mx = g_cmax[item * PN + q];
    size_t base = ((size_t)(item * PN + q)) * (size_t)PN;
    int cnt = 0;
    float s = 0.f;
    for (int p0 = 0; p0 < PN; p0 += 32) {
        float d = Lt[p0 + lane] - mx;
        bool live = (d > -25.f);
        float e = live ? __expf(d) : 0.f;
        s += e;
        float w = e * mm[p0 + lane];
        bool st = (w > 0.f);
        unsigned msk = __ballot_sync(0xffffffffu, st);
        if (st) {
            int rank = __popc(msk & ((1u << lane) - 1u));
            g_sp[base + cnt + rank] = (short)(p0 + lane);
            g_se[base + cnt + rank] = w;
        }
        cnt += __popc(msk);
    }
#pragma unroll
    for (int o = 16; o > 0; o >>= 1) s += __shfl_xor_sync(0xffffffffu, s, o);
    if (lane == 0) {
        g_nnz[item * PN + q] = cnt;
        g_cinv[item * PN + q] = 1.f / s;
    }
}

// ---------------- transpose b -> btr[(Y*128+X)][c]
__global__ void k_btr(const float* __restrict__ b) {
    __shared__ float tile[32][33];
    int tx = threadIdx.x, ty = threadIdx.y;      // 32x8
    int item = blockIdx.z >> 2, ct = blockIdx.z & 3;
    int c0 = ct * 32;
    int Yp = blockIdx.y;
    int X0 = blockIdx.x * 32;
    const float* bi = b + (size_t)item * CC * HI * HI;
    for (int j = ty; j < 32; j += 8)
        tile[j][tx] = bi[(size_t)(c0 + j) * HI * HI + Yp * HI + X0 + tx];
    __syncthreads();
    float* dst = g_btr + ((size_t)item * HI * HI) * CC;
    for (int j = ty; j < 32; j += 8)
        dst[(size_t)(Yp * HI + X0 + j) * CC + c0 + tx] = tile[tx][j];
}

// ---------------- sparse deconv gather: block per output pixel (Y,X)
__global__ __launch_bounds__(128) void k_gather() {
    int yx = blockIdx.x;
    int Y = yx >> 7, X = yx & 127;
    int item = blockIdx.y;
    int c = threadIdx.x;
    const float* btr = g_btr + ((size_t)item * HI * HI) * CC;
    float acc = 0.f;
    int pky = (Y + 1) & 1, pkx = (X + 1) & 1;
#pragma unroll
    for (int a = 0; a < 2; a++) {
        int ky = pky + 2 * a;
        int yn = Y + 1 - ky;
        if (yn < 0) continue;
        int yy = yn >> 1;
        if (yy >= 64) continue;
#pragma unroll
        for (int bb = 0; bb < 2; bb++) {
            int kx = pkx + 2 * bb;
            int xn = X + 1 - kx;
            if (xn < 0) continue;
            int xx = xn >> 1;
            if (xx >= 64) continue;
            int q = yy * 64 + xx;
            int nnzq = g_nnz[item * PN + q];
            float cq = 0.25f * g_cinv[item * PN + q];
            size_t base = ((size_t)(item * PN + q)) * (size_t)PN;
            for (int i = 0; i < nnzq; i++) {
                int p = g_sp[base + i];
                float w = g_se[base + i] * cq;
                int ph = p >> 6, pw = p & 63;
                int Yp = 2 * ph - 1 + ky;
                int Xp = 2 * pw - 1 + kx;
                if ((unsigned)Yp < 128u && (unsigned)Xp < 128u)
                    acc += w * btr[(size_t)(Yp * HI + Xp) * CC + c];
            }
        }
    }
    g_O[((size_t)item * HI * HI + yx) * CC + c] = acc;
}

// ---------------- final transpose O[yx][c] -> out[c][yx]
__global__ void k_fin(float* __restrict__ out) {
    __shared__ float tile[32][33];
    int tx = threadIdx.x, ty = threadIdx.y;      // 32x8
    int yx0 = blockIdx.x * 32;
    int c0 = blockIdx.y * 32;
    int item = blockIdx.z;
    const float* src = g_O + ((size_t)item * HI * HI) * CC;
    for (int j = ty; j < 32; j += 8)
        tile[j][tx] = src[(size_t)(yx0 + j) * CC + c0 + tx];
    __syncthreads();
    float* dst = out + (size_t)item * CC * HI * HI;
    for (int j = ty; j < 32; j += 8)
        dst[(size_t)(c0 + j) * HI * HI + yx0 + tx] = tile[tx][j];
}

// ---------------------------------------------------------------- launcher
extern "C" void kernel_launch(void* const* d_in, const int* in_sizes, int n_in,
                              void* d_out, int out_size) {
    const float* f = (const float*)d_in[0];
    const float* b = (const float*)d_in[1];
    const float* mask = (const float*)d_in[2];
    float* out = (float*)d_out;

    float* pS;
    __nv_bfloat16 *pS0Ah, *pS0Al, *pS0Bh, *pS0Bl;
    cudaGetSymbolAddress((void**)&pS, g_S);
    cudaGetSymbolAddress((void**)&pS0Ah, g_S0Ah);
    cudaGetSymbolAddress((void**)&pS0Al, g_S0Al);
    cudaGetSymbolAddress((void**)&pS0Bh, g_S0Bh);
    cudaGetSymbolAddress((void**)&pS0Bl, g_S0Bl);

    cudaFuncSetAttribute(mma_gemm, cudaFuncAttributeMaxDynamicSharedMemorySize, GSMEM);

    k_pack<<<(NITEM * CC * PN) / 256, 256>>>(f, b);
    k_stats<<<dim3(PN / 256, NITEM), 256>>>(mask);
    k_norm<<<dim3(PN / 256, NITEM), 256>>>();
    k_btr<<<dim3(4, HI, NITEM * 4), dim3(32, 8)>>>(b);

    // S0[p][q] = sum_c Bd[c][p]*Fd[c][q]  (M=N=4096, K=128)
    mma_gemm<<<dim3(32, 32, NITEM), 256, GSMEM>>>(
        pS0Ah, pS0Al, pS0Bh, pS0Bl, pS, PN, PN, CC,
        (size_t)PN * CC, (size_t)CC * PN, (size_t)PN * PN);

    k_tap9v<<<dim3(PN * PN / 1024, NITEM), 256>>>();
    k_fuse1v<<<dim3(PN * PN / 1024, NITEM), 256>>>();
    k_fz<<<dim3(PN / 32, NITEM), 256>>>();
    k_esum<<<dim3(PN / 8, NITEM), 256>>>();

    k_gather<<<dim3(HI * HI, NITEM), 128>>>();
    k_fin<<<dim3(HI * HI / 32, CC / 32, NITEM), dim3(32, 8)>>>(out);
}

// round 7
// speedup vs baseline: 8.5870x; 1.5102x over previous
#include <cuda_runtime.h>
#include <cuda_bf16.h>
#include <math.h>
#include <stdint.h>

#define PN 4096            // 64*64 downsampled pixels/patches
#define CC 128
#define HI 128
#define NITEM 2

// ------------------------------------------------------ device scratch
__device__ __align__(128) float g_S[(size_t)NITEM * PN * PN];   // S0 -> Lt
__device__ __align__(128) float g_T[(size_t)NITEM * PN * PN];   // T
__device__ __align__(128) float g_Bd[NITEM * CC * PN];
__device__ float g_n2[NITEM * PN];
__device__ float g_inorm[NITEM * PN];
__device__ float g_mm[NITEM * PN];
__device__ float g_cmaxp[NITEM * 4 * PN];
__device__ float g_cinv[NITEM * PN];
__device__ int   g_nnz[NITEM * PN];
__device__ __align__(128) short g_sp[(size_t)NITEM * PN * PN];  // sparse p idx
__device__ __align__(128) float g_se[(size_t)NITEM * PN * PN];  // sparse e*mm
__device__ __align__(128) float g_btr[NITEM * HI * HI * CC];    // b^T [yx][c]
__device__ __align__(128) float g_O[NITEM * HI * HI * CC];      // out^T [yx][c]
__device__ __align__(128) __nv_bfloat16 g_S0Ah[NITEM * PN * CC];
__device__ __align__(128) __nv_bfloat16 g_S0Al[NITEM * PN * CC];
__device__ __align__(128) __nv_bfloat16 g_S0Bh[NITEM * CC * PN];
__device__ __align__(128) __nv_bfloat16 g_S0Bl[NITEM * CC * PN];

// ------------------------------------------------------ PTX helpers
static __device__ __forceinline__ uint32_t smem_u32(const void* p) {
    uint32_t r;
    asm("{ .reg .u64 t; cvta.to.shared.u64 t, %1; cvt.u32.u64 %0, t; }" : "=r"(r) : "l"(p));
    return r;
}
// FFMA-imm (rt_SMSP=1, 2x FADD throughput); exact: a*1.0+b == a+b
static __device__ __forceinline__ float fadd1(float a, float b) {
    float d;
    asm("fma.rn.f32 %0, %1, 0f3F800000, %2;" : "=f"(d) : "f"(a), "f"(b));
    return d;
}
#define CPA(s, g) asm volatile("cp.async.cg.shared.global [%0], [%1], 16;" :: "r"(s), "l"(g))
#define CPC() asm volatile("cp.async.commit_group;" ::: "memory")
#define CPW1() asm volatile("cp.async.wait_group 1;" ::: "memory")
#define LDSM4(R, a) \
    asm volatile("ldmatrix.sync.aligned.m8n8.x4.shared.b16 {%0,%1,%2,%3}, [%4];" \
        : "=r"((R)[0]), "=r"((R)[1]), "=r"((R)[2]), "=r"((R)[3]) : "r"(a))
#define LDSM4T(R, a) \
    asm volatile("ldmatrix.sync.aligned.m8n8.x4.trans.shared.b16 {%0,%1,%2,%3}, [%4];" \
        : "=r"((R)[0]), "=r"((R)[1]), "=r"((R)[2]), "=r"((R)[3]) : "r"(a))
#define MMA16816(D, A, B) \
    asm volatile("mma.sync.aligned.m16n8k16.row.col.f32.bf16.bf16.f32 " \
        "{%0,%1,%2,%3},{%4,%5,%6,%7},{%8,%9},{%0,%1,%2,%3};" \
        : "+f"((D)[0]), "+f"((D)[1]), "+f"((D)[2]), "+f"((D)[3]) \
        : "r"((A)[0]), "r"((A)[1]), "r"((A)[2]), "r"((A)[3]), "r"((B)[0]), "r"((B)[1]))

// ------------------------------------------------------ pack downsample
__global__ void k_pack(const float* __restrict__ f, const float* __restrict__ b) {
    int idx = blockIdx.x * blockDim.x + threadIdx.x;
    int item = idx >> 19;
    int c = (idx >> 12) & 127;
    int q = idx & 4095;
    int y = q >> 6, x = q & 63;
    size_t base = ((size_t)item * CC + c) * HI * HI + (size_t)(2 * y) * HI + 2 * x;
    float vf = f[base];
    float vb = b[base];
    g_Bd[idx] = vb;
    __nv_bfloat16 h = __float2bfloat16(vf);
    g_S0Bh[idx] = h;
    g_S0Bl[idx] = __float2bfloat16(vf - __bfloat162float(h));
    h = __float2bfloat16(vb);
    int o = (item << 19) + q * CC + c;
    g_S0Ah[o] = h;
    g_S0Al[o] = __float2bfloat16(vb - __bfloat162float(h));
}

__global__ void k_stats(const float* __restrict__ mask) {
    int p = blockIdx.x * blockDim.x + threadIdx.x;
    int item = blockIdx.y;
    const float* Bd = g_Bd + item * CC * PN;
    float s = 0.f;
    for (int c = 0; c < CC; c++) {
        float v = Bd[c * PN + p];
        s += v * v;
    }
    g_n2[item * PN + p] = s;
    int ph = p >> 6, pw = p & 63;
    const float* m = mask + (size_t)item * HI * HI;
    float ms = 0.f;
    for (int dh = -1; dh <= 1; dh++)
        for (int dw = -1; dw <= 1; dw++) {
            int yy = ph + dh, xx = pw + dw;
            if ((unsigned)yy < 64u && (unsigned)xx < 64u)
                ms += m[(2 * yy) * HI + 2 * xx];
        }
    g_mm[item * PN + p] = (ms / 9.0f == 0.0f) ? 1.0f : 0.0f;
}

__global__ void k_norm() {
    int p = blockIdx.x * blockDim.x + threadIdx.x;
    int item = blockIdx.y;
    int ph = p >> 6, pw = p & 63;
    float s = 0.f;
    for (int dh = -1; dh <= 1; dh++)
        for (int dw = -1; dw <= 1; dw++) {
            int yy = ph + dh, xx = pw + dw;
            if ((unsigned)yy < 64u && (unsigned)xx < 64u)
                s += g_n2[item * PN + yy * 64 + xx];
        }
    g_inorm[item * PN + p] = rsqrtf(s + 0.1152f);
}

// =================================================== split-bf16 MMA GEMM (S0)
#define SA 10240      // 128 rows * 40 bf16 * 2B
#define SBZ 8704      // 32 rows * 136 bf16 * 2B
#define GSMEM (6 * SA + 6 * SBZ)   // 113664

__global__ void __launch_bounds__(256) mma_gemm(
    const __nv_bfloat16* __restrict__ Ah, const __nv_bfloat16* __restrict__ Al,
    const __nv_bfloat16* __restrict__ Bh, const __nv_bfloat16* __restrict__ Bl,
    float* __restrict__ C, int M, int N, int K,
    size_t sA, size_t sB, size_t sC) {
    extern __shared__ char smem[];
    uint32_t sb = smem_u32(smem);
    int tid = threadIdx.x;
    int lane = tid & 31, wid = tid >> 5;
    int warpM = wid >> 1, warpN = wid & 1;
    int m0 = blockIdx.y * 128, n0 = blockIdx.x * 128;
    int item = blockIdx.z;
    Ah += item * sA; Al += item * sA;
    Bh += item * sB; Bl += item * sB;
    C += item * sC;

    float acc[2][8][4];
#pragma unroll
    for (int i = 0; i < 2; i++)
#pragma unroll
        for (int j = 0; j < 8; j++)
#pragma unroll
            for (int v = 0; v < 4; v++) acc[i][j][v] = 0.f;

    auto load_stage = [&](int st, int kc) {
#pragma unroll
        for (int ma = 0; ma < 2; ma++) {
            const __nv_bfloat16* src = ma ? Al : Ah;
            uint32_t sbase = sb + (ma * 3 + st) * SA;
#pragma unroll
            for (int it = 0; it < 2; it++) {
                int idx = it * 256 + tid;
                int row = idx >> 2, seg = idx & 3;
                const void* g = src + (size_t)(m0 + row) * K + kc + seg * 8;
                CPA(sbase + (row * 40 + seg * 8) * 2, g);
            }
        }
#pragma unroll
        for (int mb = 0; mb < 2; mb++) {
            const __nv_bfloat16* src = mb ? Bl : Bh;
            uint32_t sbase = sb + 6 * SA + (mb * 3 + st) * SBZ;
#pragma unroll
            for (int it = 0; it < 2; it++) {
                int idx = it * 256 + tid;
                int row = idx >> 4, seg = idx & 15;
                const void* g = src + (size_t)(kc + row) * N + n0 + seg * 8;
                CPA(sbase + (row * 136 + seg * 8) * 2, g);
            }
        }
        CPC();
    };

    load_stage(0, 0);
    load_stage(1, 32);
    int NC = K >> 5;
    for (int c = 0; c < NC; c++) {
        CPW1();
        __syncthreads();
        int nc = c + 2;
        if (nc < NC) {
            int sidx = nc % 3;
            load_stage(sidx, nc << 5);
        } else {
            CPC();
        }
        int st = c % 3;
        uint32_t baseAh = sb + st * SA;
        uint32_t baseAl = sb + (3 + st) * SA;
        uint32_t baseBh = sb + 6 * SA + st * SBZ;
        uint32_t baseBl = sb + 6 * SA + (3 + st) * SBZ;
#pragma unroll
        for (int kk = 0; kk < 2; kk++) {
            uint32_t ah[2][4], al[2][4], bh[4][4], bl[4][4];
#pragma unroll
            for (int mb = 0; mb < 2; mb++) {
                uint32_t a = ((warpM * 32 + mb * 16 + (lane & 15)) * 40 + kk * 16 + (lane >> 4) * 8) * 2;
                LDSM4(ah[mb], baseAh + a);
                LDSM4(al[mb], baseAl + a);
            }
#pragma unroll
            for (int nb = 0; nb < 4; nb++) {
                uint32_t a = ((kk * 16 + (lane & 15)) * 136 + warpN * 64 + nb * 16 + (lane >> 4) * 8) * 2;
                LDSM4T(bh[nb], baseBh + a);
                LDSM4T(bl[nb], baseBl + a);
            }
#pragma unroll
            for (int mb = 0; mb < 2; mb++)
#pragma unroll
                for (int nb = 0; nb < 4; nb++)
#pragma unroll
                    for (int h = 0; h < 2; h++) {
                        float* D = acc[mb][nb * 2 + h];
                        MMA16816(D, ah[mb], &bh[nb][h * 2]);
                        MMA16816(D, ah[mb], &bl[nb][h * 2]);
                        MMA16816(D, al[mb], &bh[nb][h * 2]);
                    }
        }
    }
    int g = lane >> 2, tg = lane & 3;
#pragma unroll
    for (int mb = 0; mb < 2; mb++)
#pragma unroll
        for (int j = 0; j < 8; j++) {
            int row = m0 + warpM * 32 + mb * 16 + g;
            int col = n0 + warpN * 64 + j * 8 + tg * 2;
            float2 v0 = make_float2(acc[mb][j][0], acc[mb][j][1]);
            float2 v1 = make_float2(acc[mb][j][2], acc[mb][j][3]);
            *(float2*)&C[(size_t)row * N + col] = v0;
            *(float2*)&C[(size_t)(row + 8) * N + col] = v1;
        }
}

// ------------------------ vectorized 9-tap diagonal gather + normalize
__global__ __launch_bounds__(256) void k_tap9v() {
    int vid = blockIdx.x * 256 + threadIdx.x;
    int item = blockIdx.y;
    int p = vid >> 10;
    int q0 = (vid & 1023) << 2;
    int ph = p >> 6, pw = p & 63, qh = q0 >> 6, qw0 = q0 & 63;
    const float* S = g_S + (size_t)item * PN * PN;
    float4 acc = make_float4(0.f, 0.f, 0.f, 0.f);
    bool pm = (pw >= 1), pp_ = (pw <= 62);
#pragma unroll
    for (int dh = -1; dh <= 1; dh++) {
        if ((unsigned)(ph + dh) >= 64u || (unsigned)(qh + dh) >= 64u) continue;
        size_t a = (size_t)p * PN + q0 + (size_t)((long)dh * (64 * PN + 64));
        float4 Cv = *(const float4*)&S[a];
        acc.x = fadd1(Cv.x, acc.x); acc.y = fadd1(Cv.y, acc.y);
        acc.z = fadd1(Cv.z, acc.z); acc.w = fadd1(Cv.w, acc.w);
        if (pm) {
            float4 Mv = *(const float4*)&S[a - PN];
            float ml = (qw0 >= 1) ? S[a - PN - 1] : 0.f;
            acc.x = fadd1(ml, acc.x);   acc.y = fadd1(Mv.x, acc.y);
            acc.z = fadd1(Mv.y, acc.z); acc.w = fadd1(Mv.z, acc.w);
        }
        if (pp_) {
            float4 Pv = *(const float4*)&S[a + PN];
            float pr = (qw0 <= 59) ? S[a + PN + 4] : 0.f;
            acc.x = fadd1(Pv.y, acc.x); acc.y = fadd1(Pv.z, acc.y);
            acc.z = fadd1(Pv.w, acc.z); acc.w = fadd1(pr, acc.w);
        }
    }
    float in_ = g_inorm[item * PN + p];
    acc.x *= in_; acc.y *= in_; acc.z *= in_; acc.w *= in_;
    *(float4*)&g_T[(size_t)item * PN * PN + (size_t)p * PN + q0] = acc;
}

// ---------------- fused fuse1 + fuse2 + column max
// F1 computed on the fly from T (3 taps, flat boundaries); Z = transposed-flat
// 3-tap of F1; logits written TRANSPOSED into g_S; partial col max per segment.
__global__ __launch_bounds__(256) void k_fz() {
    int lane = threadIdx.x & 31, r = threadIdx.x >> 5;
    int q0 = blockIdx.x * 32;
    int q = q0 + lane;
    int seg = blockIdx.y;                 // 4 p-segments of 1024
    int item = blockIdx.z;
    const float* T = g_T + (size_t)item * PN * PN;
    float* Lt = g_S + (size_t)item * PN * PN;
    const float* mm = g_mm + item * PN;
    bool qIn = (q >= 64 && q < PN - 64);
    int rq = (q & 63) * 64 + (q >> 6);
    float mx = -1e30f;
    __shared__ float tile[32][33];
    __shared__ float red[8][32];

    auto f1 = [&](int rr, int cc) -> float {
        size_t i = (size_t)rr * PN + cc;
        float s = T[i];
        if (rr > 0 && cc > 0) s = fadd1(T[i - PN - 1], s);
        if (rr < PN - 1 && cc < PN - 1) s = fadd1(T[i + PN + 1], s);
        return s;
    };

    int pbeg = seg * 1024, pend = pbeg + 1024;
    for (int pt = pbeg; pt < pend; pt += 32) {
#pragma unroll
        for (int s4 = 0; s4 < 4; s4++) {
            int p = pt + s4 * 8 + r;
            float s;
            if (qIn && p >= 64 && p < PN - 64) {
                s = fadd1(f1(p - 64, q - 64), fadd1(f1(p + 64, q + 64), f1(p, q)));
            } else {
                int rp = (p & 63) * 64 + (p >> 6);
                s = 0.f;
#pragma unroll
                for (int j = -1; j <= 1; j++) {
                    int tp = rp + j, tq = rq + j;
                    if ((unsigned)tp < (unsigned)PN && (unsigned)tq < (unsigned)PN) {
                        int pp = (tp & 63) * 64 + (tp >> 6);
                        int qq = (tq & 63) * 64 + (tq >> 6);
                        s = fadd1(f1(pp, qq), s);
                    }
                }
            }
            float l = 10.f * s * mm[p];
            tile[s4 * 8 + r][lane] = l;
            mx = fmaxf(mx, l);
        }
        __syncthreads();
#pragma unroll
        for (int k = 0; k < 4; k++) {
            int qq = r * 4 + k;
            Lt[(size_t)(q0 + qq) * PN + pt + lane] = tile[lane][qq];
        }
        __syncthreads();
    }
    red[r][lane] = mx;
    __syncthreads();
    if (threadIdx.x < 32) {
        float m = red[0][threadIdx.x];
#pragma unroll
        for (int i = 1; i < 8; i++) m = fmaxf(m, red[i][threadIdx.x]);
        g_cmaxp[(item * 4 + seg) * PN + q0 + threadIdx.x] = m;
    }
}

// ---------------- exp + sum + sparse compaction (warp per column q)
__global__ __launch_bounds__(256) void k_esum() {
    int lane = threadIdx.x & 31, wid = threadIdx.x >> 5;
    int q = blockIdx.x * 8 + wid;
    int item = blockIdx.y;
    const float* Lt = g_S + (size_t)item * PN * PN + (size_t)q * PN;
    const float* mm = g_mm + item * PN;
    float mx = fmaxf(fmaxf(g_cmaxp[(item * 4 + 0) * PN + q], g_cmaxp[(item * 4 + 1) * PN + q]),
                     fmaxf(g_cmaxp[(item * 4 + 2) * PN + q], g_cmaxp[(item * 4 + 3) * PN + q]));
    size_t base = ((size_t)(item * PN + q)) * (size_t)PN;
    int cnt = 0;
    float s = 0.f;
    for (int p0 = 0; p0 < PN; p0 += 32) {
        float d = Lt[p0 + lane] - mx;
        bool live = (d > -25.f);
        float e = live ? __expf(d) : 0.f;
        s += e;
        float w = e * mm[p0 + lane];
        bool st = (w > 0.f);
        unsigned msk = __ballot_sync(0xffffffffu, st);
        if (st) {
            int rank = __popc(msk & ((1u << lane) - 1u));
            g_sp[base + cnt + rank] = (short)(p0 + lane);
            g_se[base + cnt + rank] = w;
        }
        cnt += __popc(msk);
    }
#pragma unroll
    for (int o = 16; o > 0; o >>= 1) s += __shfl_xor_sync(0xffffffffu, s, o);
    if (lane == 0) {
        g_nnz[item * PN + q] = cnt;
        g_cinv[item * PN + q] = 1.f / s;
    }
}

// ---------------- transpose b -> btr[(Y*128+X)][c]
__global__ void k_btr(const float* __restrict__ b) {
    __shared__ float tile[32][33];
    int tx = threadIdx.x, ty = threadIdx.y;      // 32x8
    int item = blockIdx.z >> 2, ct = blockIdx.z & 3;
    int c0 = ct * 32;
    int Yp = blockIdx.y;
    int X0 = blockIdx.x * 32;
    const float* bi = b + (size_t)item * CC * HI * HI;
    for (int j = ty; j < 32; j += 8)
        tile[j][tx] = bi[(size_t)(c0 + j) * HI * HI + Yp * HI + X0 + tx];
    __syncthreads();
    float* dst = g_btr + ((size_t)item * HI * HI) * CC;
    for (int j = ty; j < 32; j += 8)
        dst[(size_t)(Yp * HI + X0 + j) * CC + c0 + tx] = tile[tx][j];
}

// ---------------- sparse deconv gather: block per output pixel (Y,X)
__global__ __launch_bounds__(128) void k_gather() {
    int yx = blockIdx.x;
    int Y = yx >> 7, X = yx & 127;
    int item = blockIdx.y;
    int c = threadIdx.x;
    const float* btr = g_btr + ((size_t)item * HI * HI) * CC;
    float acc = 0.f;
    int pky = (Y + 1) & 1, pkx = (X + 1) & 1;
#pragma unroll
    for (int a = 0; a < 2; a++) {
        int ky = pky + 2 * a;
        int yn = Y + 1 - ky;
        if (yn < 0) continue;
        int yy = yn >> 1;
        if (yy >= 64) continue;
#pragma unroll
        for (int bb = 0; bb < 2; bb++) {
            int kx = pkx + 2 * bb;
            int xn = X + 1 - kx;
            if (xn < 0) continue;
            int xx = xn >> 1;
            if (xx >= 64) continue;
            int q = yy * 64 + xx;
            int nnzq = g_nnz[item * PN + q];
            float cq = 0.25f * g_cinv[item * PN + q];
            size_t base = ((size_t)(item * PN + q)) * (size_t)PN;
            for (int i = 0; i < nnzq; i++) {
                int p = g_sp[base + i];
                float w = g_se[base + i] * cq;
                int ph = p >> 6, pw = p & 63;
                int Yp = 2 * ph - 1 + ky;
                int Xp = 2 * pw - 1 + kx;
                if ((unsigned)Yp < 128u && (unsigned)Xp < 128u)
                    acc += w * btr[(size_t)(Yp * HI + Xp) * CC + c];
            }
        }
    }
    g_O[((size_t)item * HI * HI + yx) * CC + c] = acc;
}

// ---------------- final transpose O[yx][c] -> out[c][yx]
__global__ void k_fin(float* __restrict__ out) {
    __shared__ float tile[32][33];
    int tx = threadIdx.x, ty = threadIdx.y;      // 32x8
    int yx0 = blockIdx.x * 32;
    int c0 = blockIdx.y * 32;
    int item = blockIdx.z;
    const float* src = g_O + ((size_t)item * HI * HI) * CC;
    for (int j = ty; j < 32; j += 8)
        tile[j][tx] = src[(size_t)(yx0 + j) * CC + c0 + tx];
    __syncthreads();
    float* dst = out + (size_t)item * CC * HI * HI;
    for (int j = ty; j < 32; j += 8)
        dst[(size_t)(c0 + j) * HI * HI + yx0 + tx] = tile[tx][j];
}

// ---------------------------------------------------------------- launcher
extern "C" void kernel_launch(void* const* d_in, const int* in_sizes, int n_in,
                              void* d_out, int out_size) {
    const float* f = (const float*)d_in[0];
    const float* b = (const float*)d_in[1];
    const float* mask = (const float*)d_in[2];
    float* out = (float*)d_out;

    float* pS;
    __nv_bfloat16 *pS0Ah, *pS0Al, *pS0Bh, *pS0Bl;
    cudaGetSymbolAddress((void**)&pS, g_S);
    cudaGetSymbolAddress((void**)&pS0Ah, g_S0Ah);
    cudaGetSymbolAddress((void**)&pS0Al, g_S0Al);
    cudaGetSymbolAddress((void**)&pS0Bh, g_S0Bh);
    cudaGetSymbolAddress((void**)&pS0Bl, g_S0Bl);

    cudaFuncSetAttribute(mma_gemm, cudaFuncAttributeMaxDynamicSharedMemorySize, GSMEM);

    k_pack<<<(NITEM * CC * PN) / 256, 256>>>(f, b);
    k_stats<<<dim3(PN / 256, NITEM), 256>>>(mask);
    k_norm<<<dim3(PN / 256, NITEM), 256>>>();
    k_btr<<<dim3(4, HI, NITEM * 4), dim3(32, 8)>>>(b);

    // S0[p][q] = sum_c Bd[c][p]*Fd[c][q]  (M=N=4096, K=128)
    mma_gemm<<<dim3(32, 32, NITEM), 256, GSMEM>>>(
        pS0Ah, pS0Al, pS0Bh, pS0Bl, pS, PN, PN, CC,
        (size_t)PN * CC, (size_t)CC * PN, (size_t)PN * PN);

    k_tap9v<<<dim3(PN * PN / 1024, NITEM), 256>>>();
    k_fz<<<dim3(PN / 32, 4, NITEM), 256>>>();
    k_esum<<<dim3(PN / 8, NITEM), 256>>>();

    k_gather<<<dim3(HI * HI, NITEM), 128>>>();
    k_fin<<<dim3(HI * HI / 32, CC / 32, NITEM), dim3(32, 8)>>>(out);
}